// round 12
// baseline (speedup 1.0000x reference)
#include <cuda_runtime.h>
#include <cuda_bf16.h>
#include <cuda_fp16.h>
#include <cstdint>
#include <math.h>

// ---------------- problem constants ----------------
#define V_NODES 100000
#define F_DIM   512
#define D_DIM   512
#define C_DIM   128
#define N1_CNT  36864
#define S1_CNT  32768
#define B1_CNT  4096
#define S2_CNT  3584
#define B2_CNT  512

#define A_SCALE 32768.0f
#define A_INV   (1.0f / 32768.0f)
#define AQ_SCALE 4194304.0f          // 2^22 for dif_mat1 -> s8
#define XQ_SCALE 32.0f               // feature -> s8
#define OUT_INV  (1.0f / 134217728.0f)  // 2^-27

// ---------------- scratch (device globals) ----------------
__device__ float g_h1  [B1_CNT * D_DIM];
__device__ float g_cat2[B2_CNT * 1024];
__device__ float g_h2  [B2_CNT * D_DIM];
__device__ int   g_gidx1[S1_CNT];
__device__ uint8_t g_a8 [(size_t)B1_CNT * S1_CNT];   // dif_mat1 * 2^22, s8
__device__ uint8_t g_xt8[(size_t)F_DIM * S1_CNT];    // X^T * 32, s8 [512,32768]
__device__ __half  g_a2 [(size_t)B2_CNT * S2_CNT];
__device__ __half  g_h1f16[(size_t)B1_CNT * D_DIM];
__device__ __half  g_c1hi[(size_t)B1_CNT * 1024];
__device__ __half  g_c1lo[(size_t)B1_CNT * 1024];
__device__ __half  g_w1h [1024 * D_DIM];
__device__ __nv_bfloat16 g_c2hi[(size_t)B2_CNT * 1024];
__device__ __nv_bfloat16 g_c2lo[(size_t)B2_CNT * 1024];
__device__ __nv_bfloat16 g_w2hi[1024 * D_DIM];
__device__ __nv_bfloat16 g_w2lo[1024 * D_DIM];

typedef unsigned long long u64t;

// ================= helpers =================
__device__ __forceinline__ uint32_t smem_u32(const void* p) {
    uint32_t a;
    asm("{ .reg .u64 t; cvta.to.shared.u64 t, %1; cvt.u32.u64 %0, t; }" : "=r"(a) : "l"(p));
    return a;
}
#define CP_ASYNC16(sm, gm) asm volatile("cp.async.cg.shared.global [%0], [%1], 16;" :: "r"(sm), "l"(gm) : "memory")
#define CP_COMMIT()        asm volatile("cp.async.commit_group;" ::: "memory")
#define CP_WAIT1()         asm volatile("cp.async.wait_group 1;" ::: "memory")
#define CP_WAIT2()         asm volatile("cp.async.wait_group 2;" ::: "memory")
#define CP_WAIT3()         asm volatile("cp.async.wait_group 3;" ::: "memory")
#define CP_WAIT4()         asm volatile("cp.async.wait_group 4;" ::: "memory")

__device__ __forceinline__ void ldsm_x4(uint32_t* r, uint32_t addr) {
    asm volatile("ldmatrix.sync.aligned.m8n8.x4.shared.b16 {%0,%1,%2,%3}, [%4];"
        : "=r"(r[0]), "=r"(r[1]), "=r"(r[2]), "=r"(r[3]) : "r"(addr));
}
__device__ __forceinline__ void ldsm_x4_t(uint32_t* r, uint32_t addr) {
    asm volatile("ldmatrix.sync.aligned.m8n8.x4.trans.shared.b16 {%0,%1,%2,%3}, [%4];"
        : "=r"(r[0]), "=r"(r[1]), "=r"(r[2]), "=r"(r[3]) : "r"(addr));
}
__device__ __forceinline__ void mma_bf16(float* d, const uint32_t* a, const uint32_t* b) {
    asm volatile("mma.sync.aligned.m16n8k16.row.col.f32.bf16.bf16.f32 "
        "{%0,%1,%2,%3}, {%4,%5,%6,%7}, {%8,%9}, {%0,%1,%2,%3};"
        : "+f"(d[0]), "+f"(d[1]), "+f"(d[2]), "+f"(d[3])
        : "r"(a[0]), "r"(a[1]), "r"(a[2]), "r"(a[3]), "r"(b[0]), "r"(b[1]));
}
__device__ __forceinline__ void mma_f16(float* d, const uint32_t* a, const uint32_t* b) {
    asm volatile("mma.sync.aligned.m16n8k16.row.col.f32.f16.f16.f32 "
        "{%0,%1,%2,%3}, {%4,%5,%6,%7}, {%8,%9}, {%0,%1,%2,%3};"
        : "+f"(d[0]), "+f"(d[1]), "+f"(d[2]), "+f"(d[3])
        : "r"(a[0]), "r"(a[1]), "r"(a[2]), "r"(a[3]), "r"(b[0]), "r"(b[1]));
}
__device__ __forceinline__ void mma_s8(int* d, const uint32_t* a, const uint32_t* b) {
    asm volatile("mma.sync.aligned.m16n8k32.row.col.s32.s8.s8.s32 "
        "{%0,%1,%2,%3}, {%4,%5,%6,%7}, {%8,%9}, {%0,%1,%2,%3};"
        : "+r"(d[0]), "+r"(d[1]), "+r"(d[2]), "+r"(d[3])
        : "r"(a[0]), "r"(a[1]), "r"(a[2]), "r"(a[3]), "r"(b[0]), "r"(b[1]));
}
__device__ __forceinline__ uint32_t pack_bf2(__nv_bfloat16 a, __nv_bfloat16 b) {
    __nv_bfloat162 t = __halves2bfloat162(a, b);
    return *reinterpret_cast<uint32_t*>(&t);
}
__device__ __forceinline__ uint32_t pack_h2(__half a, __half b) {
    __half2 t = __halves2half2(a, b);
    return *reinterpret_cast<uint32_t*>(&t);
}
__device__ __forceinline__ void split_bf(float f, __nv_bfloat16& hi, __nv_bfloat16& lo) {
    hi = __float2bfloat16(f);
    lo = __float2bfloat16(f - __bfloat162float(hi));
}
__device__ __forceinline__ void split_h(float f, __half& hi, __half& lo) {
    hi = __float2half(f);
    lo = __float2half(f - __half2float(hi));
}
__device__ __forceinline__ int q_s8(float f) {
    int q = __float2int_rn(f);
    return max(-127, min(127, q));
}
__device__ __forceinline__ uint32_t pack_s8_4(float f0, float f1, float f2, float f3) {
    int q0 = q_s8(f0), q1 = q_s8(f1), q2 = q_s8(f2), q3 = q_s8(f3);
    return (uint32_t)(q0 & 0xFF) | ((uint32_t)(q1 & 0xFF) << 8) |
           ((uint32_t)(q2 & 0xFF) << 16) | ((uint32_t)(q3 & 0xFF) << 24);
}

// ================= small kernels =================
__global__ void build_gidx_kernel(const int* __restrict__ src_nodes,
                                  const int* __restrict__ src_idx1,
                                  int* __restrict__ out, int n) {
    int k = blockIdx.x * blockDim.x + threadIdx.x;
    if (k < n) out[k] = src_nodes[src_idx1[k]];
}

__global__ void gather_cat_kernel(const float* __restrict__ src,
                                  const int* __restrict__ idx,
                                  float* __restrict__ cat) {
    int b = blockIdx.x;
    int r = idx[b];
    const float4* s = reinterpret_cast<const float4*>(src + (size_t)r * 512);
    float4* d = reinterpret_cast<float4*>(cat + (size_t)b * 1024 + 512);
    d[threadIdx.x] = s[threadIdx.x];
}

__global__ void gather_cat_split_h_kernel(const float* __restrict__ src,
                                          const int* __restrict__ idx,
                                          const int* __restrict__ map,
                                          __half* __restrict__ chi,
                                          __half* __restrict__ clo) {
    int b = blockIdx.x;
    int r = idx[b];
    if (map) r = map[r];
    float4 v = reinterpret_cast<const float4*>(src + (size_t)r * 512)[threadIdx.x];
    __half h0, h1, h2, h3, l0, l1, l2, l3;
    split_h(v.x, h0, l0); split_h(v.y, h1, l1);
    split_h(v.z, h2, l2); split_h(v.w, h3, l3);
    size_t o = (size_t)b * 1024 + 512;
    reinterpret_cast<uint2*>(chi + o)[threadIdx.x] =
        make_uint2(pack_h2(h0, h1), pack_h2(h2, h3));
    reinterpret_cast<uint2*>(clo + o)[threadIdx.x] =
        make_uint2(pack_h2(l0, l1), pack_h2(l2, l3));
}

__global__ void split_kernel(const float* __restrict__ src,
                             __nv_bfloat16* __restrict__ hi,
                             __nv_bfloat16* __restrict__ lo, int n8) {
    int i = blockIdx.x * blockDim.x + threadIdx.x;
    if (i >= n8) return;
    const float4* s = reinterpret_cast<const float4*>(src) + 2 * (size_t)i;
    float4 a = s[0], b = s[1];
    float f[8] = {a.x, a.y, a.z, a.w, b.x, b.y, b.z, b.w};
    __nv_bfloat16 h[8], l[8];
#pragma unroll
    for (int q = 0; q < 8; ++q) split_bf(f[q], h[q], l[q]);
    reinterpret_cast<uint4*>(hi)[i] = make_uint4(
        pack_bf2(h[0], h[1]), pack_bf2(h[2], h[3]),
        pack_bf2(h[4], h[5]), pack_bf2(h[6], h[7]));
    reinterpret_cast<uint4*>(lo)[i] = make_uint4(
        pack_bf2(l[0], l[1]), pack_bf2(l[2], l[3]),
        pack_bf2(l[4], l[5]), pack_bf2(l[6], l[7]));
}

// fp32 * 2^22 -> s8 (8/thread)
__global__ void scale_as8_kernel(const float* __restrict__ src,
                                 uint8_t* __restrict__ dst, int n8) {
    int i = blockIdx.x * blockDim.x + threadIdx.x;
    if (i >= n8) return;
    const float4* s = reinterpret_cast<const float4*>(src) + 2 * (size_t)i;
    float4 a = s[0], b = s[1];
    uint32_t p0 = pack_s8_4(a.x * AQ_SCALE, a.y * AQ_SCALE, a.z * AQ_SCALE, a.w * AQ_SCALE);
    uint32_t p1 = pack_s8_4(b.x * AQ_SCALE, b.y * AQ_SCALE, b.z * AQ_SCALE, b.w * AQ_SCALE);
    reinterpret_cast<uint2*>(dst)[i] = make_uint2(p0, p1);
}

__global__ void scale_f16_kernel(const float* __restrict__ src,
                                 __half* __restrict__ dst, int n8) {
    int i = blockIdx.x * blockDim.x + threadIdx.x;
    if (i >= n8) return;
    const float4* s = reinterpret_cast<const float4*>(src) + 2 * (size_t)i;
    float4 a = s[0], b = s[1];
    float f[8] = {a.x, a.y, a.z, a.w, b.x, b.y, b.z, b.w};
    __half h[8];
#pragma unroll
    for (int q = 0; q < 8; ++q) h[q] = __float2half(f[q] * A_SCALE);
    reinterpret_cast<uint4*>(dst)[i] = make_uint4(
        pack_h2(h[0], h[1]), pack_h2(h[2], h[3]),
        pack_h2(h[4], h[5]), pack_h2(h[6], h[7]));
}

__global__ void f32_to_f16_kernel(const float* __restrict__ src,
                                  __half* __restrict__ dst, int n4) {
    int i = blockIdx.x * blockDim.x + threadIdx.x;
    if (i >= n4) return;
    float4 v = reinterpret_cast<const float4*>(src)[i];
    reinterpret_cast<uint2*>(dst)[i] =
        make_uint2(pack_h2(__float2half(v.x), __float2half(v.y)),
                   pack_h2(__float2half(v.z), __float2half(v.w)));
}

// gather + transpose + s8 quant: XT[n][k] = s8(features[gidx[k]][n] * 32)
__global__ void prep_xt8_kernel(const float* __restrict__ features,
                                const int* __restrict__ gidx,
                                uint8_t* __restrict__ xt) {
    __shared__ float tile[128][65];
    const int k0 = blockIdx.x * 128;
    const int n0 = blockIdx.y * 64;
    const int tid = threadIdx.x;
    for (int i = tid; i < 128 * 16; i += 128) {
        int r = i >> 4, c4 = i & 15;
        float4 v = *reinterpret_cast<const float4*>(
            features + (size_t)gidx[k0 + r] * F_DIM + n0 + c4 * 4);
        tile[r][c4 * 4 + 0] = v.x; tile[r][c4 * 4 + 1] = v.y;
        tile[r][c4 * 4 + 2] = v.z; tile[r][c4 * 4 + 3] = v.w;
    }
    __syncthreads();
    for (int i = tid; i < 64 * 32; i += 128) {
        int n = i >> 5, kg = i & 31;
        uint32_t p = pack_s8_4(tile[kg * 4 + 0][n] * XQ_SCALE,
                               tile[kg * 4 + 1][n] * XQ_SCALE,
                               tile[kg * 4 + 2][n] * XQ_SCALE,
                               tile[kg * 4 + 3][n] * XQ_SCALE);
        *reinterpret_cast<uint32_t*>(xt + (size_t)(n0 + n) * S1_CNT + k0 + kg * 4) = p;
    }
}

// ================= GEMM1: s8 IMMA, 512 thr, 5-stage, hoisted offsets =================
#define P_A_TILE 16384
#define P_B_TILE 16384
#define P_STAGE  (P_A_TILE + P_B_TILE)   // 32KB
#define P_NSTG   5
#define P_SMEM   (P_NSTG * P_STAGE)      // 160KB

__global__ __launch_bounds__(512, 1)
void gemm1_s8(const uint8_t* __restrict__ A,
              const uint8_t* __restrict__ Bt,
              __half* __restrict__ Chi,
              __half* __restrict__ Clo) {
    constexpr int NCHUNK = S1_CNT / 128;   // 256
    constexpr int LDC = 1024;
    extern __shared__ __align__(128) char smem[];
    const uint32_t sb = smem_u32(smem);
    const int tid = threadIdx.x;
    const int wid = tid >> 5;
    const int lane = tid & 31;
    const int bm = blockIdx.y * 128;
    const int bn = blockIdx.x * 128;
    const int wm = (wid & 3) * 32;
    const int wn = (wid >> 2) * 32;

    int acc[2][4][4];
#pragma unroll
    for (int m = 0; m < 2; ++m)
#pragma unroll
        for (int n = 0; n < 4; ++n)
#pragma unroll
            for (int j = 0; j < 4; ++j) acc[m][n][j] = 0;

    // persistent cp.async source pointers
    int rA0 = tid >> 3,          sA0 = tid & 7;
    int rA1 = (tid + 512) >> 3,  sA1 = (tid + 512) & 7;
    const uint8_t* aP0 = A + (size_t)(bm + rA0) * S1_CNT + sA0 * 16;
    const uint8_t* aP1 = A + (size_t)(bm + rA1) * S1_CNT + sA1 * 16;
    const uint8_t* bP0 = Bt + (size_t)(bn + rA0) * S1_CNT + sA0 * 16;
    const uint8_t* bP1 = Bt + (size_t)(bn + rA1) * S1_CNT + sA1 * 16;
    const uint32_t dA0 = rA0 * 128 + ((sA0 ^ (rA0 & 7)) << 4);
    const uint32_t dA1 = rA1 * 128 + ((sA1 ^ (rA1 & 7)) << 4);

    // hoisted ldsm offsets (stage-invariant)
    const uint32_t mrow0 = wm + (lane & 15);
    const uint32_t mrow1 = mrow0 + 16;
    const uint32_t acol  = (lane >> 4);
    const uint32_t nrow0 = wn + (lane & 7) + ((lane & 16) >> 1);
    const uint32_t nrow1 = nrow0 + 16;
    const uint32_t bcol  = (lane >> 3) & 1;
    uint32_t offA[2][4], offB[2][4];
#pragma unroll
    for (int kk = 0; kk < 4; ++kk) {
        uint32_t cA = (uint32_t)(kk * 2) + acol;
        uint32_t cB = (uint32_t)(kk * 2) + bcol;
        offA[0][kk] = mrow0 * 128 + ((cA ^ (mrow0 & 7)) << 4);
        offA[1][kk] = mrow1 * 128 + ((cA ^ (mrow1 & 7)) << 4);
        offB[0][kk] = P_A_TILE + nrow0 * 128 + ((cB ^ (nrow0 & 7)) << 4);
        offB[1][kk] = P_A_TILE + nrow1 * 128 + ((cB ^ (nrow1 & 7)) << 4);
    }

#define P_LOAD(pred, sbase) do {                                              \
    if (pred) {                                                               \
        CP_ASYNC16((sbase) + dA0, aP0);                                       \
        CP_ASYNC16((sbase) + dA1, aP1);                                       \
        CP_ASYNC16((sbase) + P_A_TILE + dA0, bP0);                            \
        CP_ASYNC16((sbase) + P_A_TILE + dA1, bP1);                            \
    }                                                                         \
    CP_COMMIT();                                                              \
    aP0 += 128; aP1 += 128; bP0 += 128; bP1 += 128;                           \
} while (0)

    P_LOAD(true, sb + 0 * P_STAGE);
    P_LOAD(true, sb + 1 * P_STAGE);
    P_LOAD(true, sb + 2 * P_STAGE);
    P_LOAD(true, sb + 3 * P_STAGE);

    uint32_t cmp_base = sb;
    uint32_t load_base = sb + 4 * P_STAGE;
    const uint32_t smem_end = sb + P_NSTG * P_STAGE;

#pragma unroll 1
    for (int ch = 0; ch < NCHUNK; ++ch) {
        CP_WAIT3();
        __syncthreads();
        P_LOAD(ch + 4 < NCHUNK, load_base);
        load_base += P_STAGE; if (load_base == smem_end) load_base = sb;

        const uint32_t abase = cmp_base;
#pragma unroll
        for (int kk = 0; kk < 4; ++kk) {
            uint32_t ar[2][4], br[2][4];
            ldsm_x4(ar[0], abase + offA[0][kk]);
            ldsm_x4(ar[1], abase + offA[1][kk]);
            ldsm_x4(br[0], abase + offB[0][kk]);
            ldsm_x4(br[1], abase + offB[1][kk]);
#pragma unroll
            for (int m = 0; m < 2; ++m)
#pragma unroll
                for (int j = 0; j < 2; ++j)
#pragma unroll
                    for (int h = 0; h < 2; ++h)
                        mma_s8(acc[m][j * 2 + h], ar[m], &br[j][2 * h]);
        }
        cmp_base += P_STAGE; if (cmp_base == smem_end) cmp_base = sb;
    }

    // epilogue: int -> float scale + fp16 hi/lo split
#pragma unroll
    for (int m = 0; m < 2; ++m) {
#pragma unroll
        for (int half = 0; half < 2; ++half) {
            const int row = bm + wm + m * 16 + half * 8 + (lane >> 2);
#pragma unroll
            for (int n8 = 0; n8 < 4; ++n8) {
                const int col = bn + wn + n8 * 8 + (lane & 3) * 2;
                float v0 = (float)acc[m][n8][2 * half + 0] * OUT_INV;
                float v1 = (float)acc[m][n8][2 * half + 1] * OUT_INV;
                __half h0, h1, l0, l1;
                split_h(v0, h0, l0);
                split_h(v1, h1, l1);
                size_t o = (size_t)row * LDC + col;
                *reinterpret_cast<uint32_t*>(Chi + o) = pack_h2(h0, h1);
                *reinterpret_cast<uint32_t*>(Clo + o) = pack_h2(l0, l1);
            }
        }
    }
#undef P_LOAD
}

// ================= 2-term fp16 GEMM: C = relu((Ahi+Alo) @ B), K=1024 =================
#define T_A_TILE 16384
#define T_B_TILE 16384
#define T_STAGE  (2 * T_A_TILE + T_B_TILE)
#define T_NSTG   4
#define T_SMEM   (T_NSTG * T_STAGE)

__global__ __launch_bounds__(256, 1)
void gemm_2t_f16(const __half* __restrict__ Ahi,
                 const __half* __restrict__ Alo,
                 const __half* __restrict__ B,
                 float* __restrict__ C,
                 __half* __restrict__ C16) {
    constexpr int NCHUNK = 16;
    constexpr int LDA = 1024, LDB = 512, LDC = 512;
    extern __shared__ __align__(128) char smem[];
    const uint32_t sb = smem_u32(smem);
    const int tid = threadIdx.x;
    const int wid = tid >> 5;
    const int lane = tid & 31;
    const int bm = blockIdx.y * 128;
    const int bn = blockIdx.x * 128;
    const int wm = (wid & 3) * 32;
    const int wn = (wid >> 2) * 64;

    float acc[2][8][4];
#pragma unroll
    for (int m = 0; m < 2; ++m)
#pragma unroll
        for (int n = 0; n < 8; ++n)
#pragma unroll
            for (int j = 0; j < 4; ++j) acc[m][n][j] = 0.f;

#define T_LOAD(ch) do {                                                       \
    if ((ch) < NCHUNK) {                                                      \
        size_t k0 = (size_t)(ch) * 64;                                        \
        uint32_t sa = sb + (uint32_t)((ch) % T_NSTG) * T_STAGE;               \
        uint32_t sB = sa + 2 * T_A_TILE;                                      \
        _Pragma("unroll")                                                     \
        for (int i = 0; i < 4; ++i) {                                         \
            int lin = tid + i * 256;                                          \
            int row = lin >> 3, seg = lin & 7;                                \
            uint32_t d = sa + row * 128 + (((seg ^ (row & 7))) << 4);         \
            CP_ASYNC16(d, Ahi + (size_t)(bm + row) * LDA + k0 + seg * 8);     \
            CP_ASYNC16(d + T_A_TILE, Alo + (size_t)(bm + row) * LDA + k0 + seg * 8); \
        }                                                                     \
        _Pragma("unroll")                                                     \
        for (int i = 0; i < 4; ++i) {                                         \
            int lin = tid + i * 256;                                          \
            int row = lin >> 4, chk = lin & 15;                               \
            uint32_t d = sB + row * 256 + (((chk ^ (row & 7))) << 4);         \
            CP_ASYNC16(d, B + (size_t)(k0 + row) * LDB + bn + chk * 8);       \
        }                                                                     \
    }                                                                         \
    CP_COMMIT();                                                              \
} while (0)

    T_LOAD(0); T_LOAD(1); T_LOAD(2);

    for (int ch = 0; ch < NCHUNK; ++ch) {
        CP_WAIT2();
        __syncthreads();
        T_LOAD(ch + 3);

        const uint32_t abase = sb + (uint32_t)(ch % T_NSTG) * T_STAGE;
        const uint32_t bbase = abase + 2 * T_A_TILE;
#pragma unroll
        for (int kk = 0; kk < 4; ++kk) {
            uint32_t ah[2][4], al[2][4];
#pragma unroll
            for (int m = 0; m < 2; ++m) {
                uint32_t r = wm + m * 16 + (lane & 15);
                uint32_t c = kk * 2 + (lane >> 4);
                uint32_t ad = abase + r * 128 + ((c ^ (r & 7)) << 4);
                ldsm_x4(ah[m], ad);
                ldsm_x4(al[m], ad + T_A_TILE);
            }
            uint32_t bh[4][4];
#pragma unroll
            for (int j = 0; j < 4; ++j) {
                uint32_t krow = kk * 16 + (lane & 15);
                uint32_t chk = (uint32_t)(wn >> 3) + j * 2 + (lane >> 4);
                ldsm_x4_t(bh[j], bbase + krow * 256 + ((chk ^ (krow & 7)) << 4));
            }
#pragma unroll
            for (int m = 0; m < 2; ++m)
#pragma unroll
                for (int j = 0; j < 4; ++j)
#pragma unroll
                    for (int h = 0; h < 2; ++h) {
                        const int n8 = j * 2 + h;
                        mma_f16(acc[m][n8], ah[m], &bh[j][2 * h]);
                        mma_f16(acc[m][n8], al[m], &bh[j][2 * h]);
                    }
        }
        __syncthreads();
    }

#pragma unroll
    for (int m = 0; m < 2; ++m) {
        const int row = bm + wm + m * 16 + (lane >> 2);
#pragma unroll
        for (int n8 = 0; n8 < 8; ++n8) {
            const int col = bn + wn + n8 * 8 + (lane & 3) * 2;
            float2 v0 = make_float2(fmaxf(acc[m][n8][0], 0.f), fmaxf(acc[m][n8][1], 0.f));
            float2 v1 = make_float2(fmaxf(acc[m][n8][2], 0.f), fmaxf(acc[m][n8][3], 0.f));
            *reinterpret_cast<float2*>(C + (size_t)row * LDC + col) = v0;
            *reinterpret_cast<float2*>(C + (size_t)(row + 8) * LDC + col) = v1;
            if (C16) {
                *reinterpret_cast<uint32_t*>(C16 + (size_t)row * LDC + col) =
                    pack_h2(__float2half(v0.x), __float2half(v0.y));
                *reinterpret_cast<uint32_t*>(C16 + (size_t)(row + 8) * LDC + col) =
                    pack_h2(__float2half(v1.x), __float2half(v1.y));
            }
        }
    }
#undef T_LOAD
}

// ================= GEMM2 (agg2): fp16 single, gathered B =================
#define Q_A_TILE 16384
#define Q_B_TILE 16384
#define Q_STAGE  (Q_A_TILE + Q_B_TILE)
#define Q_NSTG   6
#define Q_SMEM   (Q_NSTG * Q_STAGE)

__global__ __launch_bounds__(256, 1)
void gemm2_f16(const __half* __restrict__ A,
               const __half* __restrict__ B,
               const int* __restrict__ gidx,
               float* __restrict__ C) {
    constexpr int NCHUNK = S2_CNT / 64;
    constexpr int LDA = S2_CNT, LDB = D_DIM, LDC = 1024;
    extern __shared__ __align__(128) char smem[];
    const uint32_t sb = smem_u32(smem);
    const int tid = threadIdx.x;
    const int wid = tid >> 5;
    const int lane = tid & 31;
    const int bm = blockIdx.y * 128;
    const int bn = blockIdx.x * 128;
    const int wm = (wid & 3) * 32;
    const int wn = (wid >> 2) * 64;

    float acc[2][8][4];
#pragma unroll
    for (int m = 0; m < 2; ++m)
#pragma unroll
        for (int n = 0; n < 8; ++n)
#pragma unroll
            for (int j = 0; j < 4; ++j) acc[m][n][j] = 0.f;

#define Q_LOAD(ch) do {                                                       \
    if ((ch) < NCHUNK) {                                                      \
        size_t k0 = (size_t)(ch) * 64;                                        \
        uint32_t sa = sb + (uint32_t)((ch) % Q_NSTG) * Q_STAGE;               \
        uint32_t sB = sa + Q_A_TILE;                                          \
        _Pragma("unroll")                                                     \
        for (int i = 0; i < 4; ++i) {                                         \
            int lin = tid + i * 256;                                          \
            int row = lin >> 3, seg = lin & 7;                                \
            uint32_t d = sa + row * 128 + (((seg ^ (row & 7))) << 4);         \
            CP_ASYNC16(d, A + (size_t)(bm + row) * LDA + k0 + seg * 8);       \
        }                                                                     \
        _Pragma("unroll")                                                     \
        for (int i = 0; i < 4; ++i) {                                         \
            int lin = tid + i * 256;                                          \
            int row = lin >> 4, chk = lin & 15;                               \
            int g = gidx[k0 + row];                                           \
            uint32_t d = sB + row * 256 + (((chk ^ (row & 7))) << 4);         \
            CP_ASYNC16(d, B + (size_t)g * LDB + bn + chk * 8);                \
        }                                                                     \
    }                                                                         \
    CP_COMMIT();                                                              \
} while (0)

    Q_LOAD(0); Q_LOAD(1); Q_LOAD(2); Q_LOAD(3); Q_LOAD(4);

    for (int ch = 0; ch < NCHUNK; ++ch) {
        CP_WAIT4();
        __syncthreads();
        Q_LOAD(ch + 5);

        const uint32_t abase = sb + (uint32_t)(ch % Q_NSTG) * Q_STAGE;
        const uint32_t bbase = abase + Q_A_TILE;
#pragma unroll
        for (int kk = 0; kk < 4; ++kk) {
            uint32_t ah[2][4];
#pragma unroll
            for (int m = 0; m < 2; ++m) {
                uint32_t r = wm + m * 16 + (lane & 15);
                uint32_t c = kk * 2 + (lane >> 4);
                ldsm_x4(ah[m], abase + r * 128 + ((c ^ (r & 7)) << 4));
            }
            uint32_t bh[4][4];
#pragma unroll
            for (int j = 0; j < 4; ++j) {
                uint32_t krow = kk * 16 + (lane & 15);
                uint32_t chk = (uint32_t)(wn >> 3) + j * 2 + (lane >> 4);
                ldsm_x4_t(bh[j], bbase + krow * 256 + ((chk ^ (krow & 7)) << 4));
            }
#pragma unroll
            for (int m = 0; m < 2; ++m)
#pragma unroll
                for (int j = 0; j < 4; ++j)
#pragma unroll
                    for (int h = 0; h < 2; ++h)
                        mma_f16(acc[m][j * 2 + h], ah[m], &bh[j][2 * h]);
        }
        __syncthreads();
    }

#pragma unroll
    for (int m = 0; m < 2; ++m) {
        const int row = bm + wm + m * 16 + (lane >> 2);
#pragma unroll
        for (int n8 = 0; n8 < 8; ++n8) {
            const int col = bn + wn + n8 * 8 + (lane & 3) * 2;
            *reinterpret_cast<float2*>(C + (size_t)row * LDC + col) =
                make_float2(acc[m][n8][0] * A_INV, acc[m][n8][1] * A_INV);
            *reinterpret_cast<float2*>(C + (size_t)(row + 8) * LDC + col) =
                make_float2(acc[m][n8][2] * A_INV, acc[m][n8][3] * A_INV);
        }
    }
#undef Q_LOAD
}

// ================= bf16 3-term GEMM (layer-2 h2) =================
#define A_TILE_B 16384
#define B_TILE_B 16384
#define STAGE_B  (2 * A_TILE_B + 2 * B_TILE_B)
#define GSMEM    (3 * STAGE_B)

__global__ __launch_bounds__(256, 1)
void gemm_hmma3(const __nv_bfloat16* __restrict__ Ahi,
                const __nv_bfloat16* __restrict__ Alo,
                const __nv_bfloat16* __restrict__ Bhi,
                const __nv_bfloat16* __restrict__ Blo,
                float* __restrict__ C) {
    constexpr int NCHUNK = 16;
    constexpr int LDA = 1024, LDB = 512, LDC = 512;
    extern __shared__ __align__(128) char smem[];
    const uint32_t sb = smem_u32(smem);
    const int tid = threadIdx.x;
    const int wid = tid >> 5;
    const int lane = tid & 31;
    const int bm = blockIdx.y * 128;
    const int bn = blockIdx.x * 128;
    const int wm = (wid & 3) * 32;
    const int wn = (wid >> 2) * 64;

    float acc[2][8][4];
#pragma unroll
    for (int m = 0; m < 2; ++m)
#pragma unroll
        for (int n = 0; n < 8; ++n)
#pragma unroll
            for (int j = 0; j < 4; ++j) acc[m][n][j] = 0.f;

#define G_LOAD(ch, stg) do {                                                  \
    if ((ch) < NCHUNK) {                                                      \
        size_t k0 = (size_t)(ch) * 64;                                        \
        uint32_t sa = sb + (uint32_t)(stg) * STAGE_B;                         \
        uint32_t sB = sa + 2 * A_TILE_B;                                      \
        _Pragma("unroll")                                                     \
        for (int i = 0; i < 4; ++i) {                                         \
            int lin = tid + i * 256;                                          \
            int row = lin >> 3, seg = lin & 7;                                \
            uint32_t d = sa + row * 128 + (((seg ^ (row & 7))) << 4);         \
            CP_ASYNC16(d, Ahi + (size_t)(bm + row) * LDA + k0 + seg * 8);     \
            CP_ASYNC16(d + A_TILE_B, Alo + (size_t)(bm + row) * LDA + k0 + seg * 8); \
        }                                                                     \
        _Pragma("unroll")                                                     \
        for (int i = 0; i < 4; ++i) {                                         \
            int lin = tid + i * 256;                                          \
            int row = lin >> 4, chk = lin & 15;                               \
            uint32_t d = sB + row * 256 + (((chk ^ (row & 7))) << 4);         \
            CP_ASYNC16(d, Bhi + (size_t)(k0 + row) * LDB + bn + chk * 8);     \
            CP_ASYNC16(d + B_TILE_B, Blo + (size_t)(k0 + row) * LDB + bn + chk * 8); \
        }                                                                     \
    }                                                                         \
    CP_COMMIT();                                                              \
} while (0)

    G_LOAD(0, 0);
    G_LOAD(1, 1);

    int stg = 0;
    for (int ch = 0; ch < NCHUNK; ++ch) {
        CP_WAIT1();
        __syncthreads();
        G_LOAD(ch + 2, (stg + 2 >= 3) ? (stg - 1) : (stg + 2));

        const uint32_t abase = sb + (uint32_t)stg * STAGE_B;
        const uint32_t bbase = abase + 2 * A_TILE_B;
#pragma unroll
        for (int kk = 0; kk < 4; ++kk) {
            uint32_t ah[2][4], al[2][4];
#pragma unroll
            for (int m = 0; m < 2; ++m) {
                uint32_t r = wm + m * 16 + (lane & 15);
                uint32_t c = kk * 2 + (lane >> 4);
                uint32_t ad = abase + r * 128 + ((c ^ (r & 7)) << 4);
                ldsm_x4(ah[m], ad);
                ldsm_x4(al[m], ad + A_TILE_B);
            }
            uint32_t bh[4][4], bl[4][4];
#pragma unroll
            for (int j = 0; j < 4; ++j) {
                uint32_t krow = kk * 16 + (lane & 15);
                uint32_t chk = (uint32_t)(wn >> 3) + j * 2 + (lane >> 4);
                uint32_t bd = bbase + krow * 256 + ((chk ^ (krow & 7)) << 4);
                ldsm_x4_t(bh[j], bd);
                ldsm_x4_t(bl[j], bd + B_TILE_B);
            }
#pragma unroll
            for (int m = 0; m < 2; ++m)
#pragma unroll
                for (int j = 0; j < 4; ++j)
#pragma unroll
                    for (int h = 0; h < 2; ++h) {
                        const int n8 = j * 2 + h;
                        mma_bf16(acc[m][n8], ah[m], &bh[j][2 * h]);
                        mma_bf16(acc[m][n8], ah[m], &bl[j][2 * h]);
                        mma_bf16(acc[m][n8], al[m], &bh[j][2 * h]);
                    }
        }
        stg = (stg + 1 == 3) ? 0 : stg + 1;
    }

#pragma unroll
    for (int m = 0; m < 2; ++m) {
        const int row = bm + wm + m * 16 + (lane >> 2);
#pragma unroll
        for (int n8 = 0; n8 < 8; ++n8) {
            const int col = bn + wn + n8 * 8 + (lane & 3) * 2;
            *reinterpret_cast<float2*>(C + (size_t)row * LDC + col) =
                make_float2(fmaxf(acc[m][n8][0], 0.f), fmaxf(acc[m][n8][1], 0.f));
            *reinterpret_cast<float2*>(C + (size_t)(row + 8) * LDC + col) =
                make_float2(fmaxf(acc[m][n8][2], 0.f), fmaxf(acc[m][n8][3], 0.f));
        }
    }
#undef G_LOAD
}

// ================= classifier + softmax =================
__global__ void cls_softmax_kernel(const float* __restrict__ h2,
                                   const float* __restrict__ wc,
                                   float* __restrict__ out) {
    __shared__ float sh[D_DIM];
    __shared__ float red[C_DIM];
    const int b = blockIdx.x;
    const int c = threadIdx.x;
    for (int i = c; i < D_DIM; i += C_DIM) sh[i] = h2[(size_t)b * D_DIM + i];
    __syncthreads();
    float acc = 0.f;
#pragma unroll 8
    for (int k = 0; k < D_DIM; ++k)
        acc = fmaf(sh[k], wc[(size_t)k * C_DIM + c], acc);
    red[c] = acc;
    __syncthreads();
    for (int s = C_DIM / 2; s > 0; s >>= 1) {
        if (c < s) red[c] = fmaxf(red[c], red[c + s]);
        __syncthreads();
    }
    float mx = red[0];
    __syncthreads();
    float e = expf(acc - mx);
    red[c] = e;
    __syncthreads();
    for (int s = C_DIM / 2; s > 0; s >>= 1) {
        if (c < s) red[c] += red[c + s];
        __syncthreads();
    }
    out[(size_t)b * C_DIM + c] = e / red[0];
}

// ================= launch =================
extern "C" void kernel_launch(void* const* d_in, const int* in_sizes, int n_in,
                              void* d_out, int out_size) {
    const float* features  = (const float*)d_in[0];
    const int*   src_nodes = (const int*)d_in[1];
    const int*   dst_idx1  = (const int*)d_in[2];
    const int*   src_idx1  = (const int*)d_in[3];
    const float* dif_mat1  = (const float*)d_in[4];
    const int*   dst_idx2  = (const int*)d_in[5];
    const int*   src_idx2  = (const int*)d_in[6];
    const float* dif_mat2  = (const float*)d_in[7];
    const float* w1        = (const float*)d_in[8];
    const float* w2        = (const float*)d_in[9];
    const float* w_cls     = (const float*)d_in[10];
    float* out = (float*)d_out;

    float *h1, *cat2, *h2;
    int* gidx1;
    uint8_t *a8, *xt8;
    __half *a2, *h1f16, *c1hi, *c1lo, *w1h;
    __nv_bfloat16 *c2hi, *c2lo, *w2hi, *w2lo;
    cudaGetSymbolAddress((void**)&h1,    g_h1);
    cudaGetSymbolAddress((void**)&cat2,  g_cat2);
    cudaGetSymbolAddress((void**)&h2,    g_h2);
    cudaGetSymbolAddress((void**)&gidx1, g_gidx1);
    cudaGetSymbolAddress((void**)&a8,    g_a8);
    cudaGetSymbolAddress((void**)&xt8,   g_xt8);
    cudaGetSymbolAddress((void**)&a2,    g_a2);
    cudaGetSymbolAddress((void**)&h1f16, g_h1f16);
    cudaGetSymbolAddress((void**)&c1hi,  g_c1hi);
    cudaGetSymbolAddress((void**)&c1lo,  g_c1lo);
    cudaGetSymbolAddress((void**)&w1h,   g_w1h);
    cudaGetSymbolAddress((void**)&c2hi,  g_c2hi);
    cudaGetSymbolAddress((void**)&c2lo,  g_c2lo);
    cudaGetSymbolAddress((void**)&w2hi,  g_w2hi);
    cudaGetSymbolAddress((void**)&w2lo,  g_w2lo);

    cudaFuncSetAttribute((const void*)gemm1_s8,
                         cudaFuncAttributeMaxDynamicSharedMemorySize, P_SMEM);
    cudaFuncSetAttribute((const void*)gemm_2t_f16,
                         cudaFuncAttributeMaxDynamicSharedMemorySize, T_SMEM);
    cudaFuncSetAttribute((const void*)gemm2_f16,
                         cudaFuncAttributeMaxDynamicSharedMemorySize, Q_SMEM);
    cudaFuncSetAttribute((const void*)gemm_hmma3,
                         cudaFuncAttributeMaxDynamicSharedMemorySize, GSMEM);

    // launches 1-3: prep so gemm1 is the 4th launch (ncu -s 5 -c 1 lands on it)
    {
        int n8 = (B1_CNT * S1_CNT) / 8;
        scale_as8_kernel<<<n8 / 256, 256>>>(dif_mat1, a8, n8);
    }
    build_gidx_kernel<<<(S1_CNT + 255) / 256, 256>>>(src_nodes, src_idx1, gidx1, S1_CNT);
    prep_xt8_kernel<<<dim3(S1_CNT / 128, F_DIM / 64), 128>>>(features, gidx1, xt8);

    // 4: agg1 -> c1hi/c1lo[:, 0:512] (s8 IMMA)
    gemm1_s8<<<dim3(F_DIM / 128, B1_CNT / 128), 512, P_SMEM>>>(a8, xt8, c1hi, c1lo);

    gather_cat_split_h_kernel<<<B1_CNT, 128>>>(features, dst_idx1, src_nodes, c1hi, c1lo);
    f32_to_f16_kernel<<<(1024 * D_DIM / 4) / 256, 256>>>(w1, w1h, 1024 * D_DIM / 4);

    gemm_2t_f16<<<dim3(D_DIM / 128, B1_CNT / 128), 256, T_SMEM>>>(c1hi, c1lo, w1h, h1, h1f16);

    {
        int a8n = (B2_CNT * S2_CNT) / 8;
        scale_f16_kernel<<<(a8n + 255) / 256, 256>>>(dif_mat2, a2, a8n);
    }
    gather_cat_kernel<<<B2_CNT, 128>>>(h1, dst_idx2, cat2);
    gemm2_f16<<<dim3(D_DIM / 128, B2_CNT / 128), 256, Q_SMEM>>>(a2, h1f16, src_idx2, cat2);
    {
        int n8 = (B2_CNT * 1024) / 8;
        split_kernel<<<(n8 + 255) / 256, 256>>>(cat2, c2hi, c2lo, n8);
        int m8 = (1024 * D_DIM) / 8;
        split_kernel<<<m8 / 256, 256>>>(w2, w2hi, w2lo, m8);
    }
    gemm_hmma3<<<dim3(D_DIM / 128, B2_CNT / 128), 256, GSMEM>>>(c2hi, c2lo, w2hi, w2lo, h2);

    cls_softmax_kernel<<<B2_CNT, C_DIM>>>(h2, w_cls, out);
}

// round 13
// speedup vs baseline: 1.8843x; 1.8843x over previous
#include <cuda_runtime.h>
#include <cuda_bf16.h>
#include <cuda_fp16.h>
#include <cstdint>
#include <math.h>

// ---------------- problem constants ----------------
#define V_NODES 100000
#define F_DIM   512
#define D_DIM   512
#define C_DIM   128
#define N1_CNT  36864
#define S1_CNT  32768
#define B1_CNT  4096
#define S2_CNT  3584
#define B2_CNT  512

#define A_SCALE 32768.0f
#define A_INV   (1.0f / 32768.0f)

// ---------------- scratch (device globals) ----------------
__device__ float g_h1  [B1_CNT * D_DIM];
__device__ float g_cat2[B2_CNT * 1024];
__device__ float g_h2  [B2_CNT * D_DIM];
__device__ int   g_gidx1[S1_CNT];
__device__ uint8_t g_a8 [(size_t)B1_CNT * S1_CNT];
__device__ uint8_t g_xt8[(size_t)F_DIM * S1_CNT];
__device__ __half  g_a2 [(size_t)B2_CNT * S2_CNT];
__device__ __half  g_h1f16[(size_t)B1_CNT * D_DIM];
__device__ __half  g_c1hi[(size_t)B1_CNT * 1024];
__device__ __half  g_c1lo[(size_t)B1_CNT * 1024];
__device__ __half  g_w1h [1024 * D_DIM];
__device__ __nv_bfloat16 g_c2hi[(size_t)B2_CNT * 1024];
__device__ __nv_bfloat16 g_c2lo[(size_t)B2_CNT * 1024];
__device__ __nv_bfloat16 g_w2hi[1024 * D_DIM];
__device__ __nv_bfloat16 g_w2lo[1024 * D_DIM];

typedef unsigned long long u64t;

// ================= helpers =================
__device__ __forceinline__ uint32_t smem_u32(const void* p) {
    uint32_t a;
    asm("{ .reg .u64 t; cvta.to.shared.u64 t, %1; cvt.u32.u64 %0, t; }" : "=r"(a) : "l"(p));
    return a;
}
#define CP_ASYNC16(sm, gm) asm volatile("cp.async.cg.shared.global [%0], [%1], 16;" :: "r"(sm), "l"(gm) : "memory")
#define CP_COMMIT()        asm volatile("cp.async.commit_group;" ::: "memory")
#define CP_WAIT1()         asm volatile("cp.async.wait_group 1;" ::: "memory")
#define CP_WAIT2()         asm volatile("cp.async.wait_group 2;" ::: "memory")
#define CP_WAIT4()         asm volatile("cp.async.wait_group 4;" ::: "memory")

__device__ __forceinline__ void ldsm_x4(uint32_t* r, uint32_t addr) {
    asm volatile("ldmatrix.sync.aligned.m8n8.x4.shared.b16 {%0,%1,%2,%3}, [%4];"
        : "=r"(r[0]), "=r"(r[1]), "=r"(r[2]), "=r"(r[3]) : "r"(addr));
}
__device__ __forceinline__ void ldsm_x4_t(uint32_t* r, uint32_t addr) {
    asm volatile("ldmatrix.sync.aligned.m8n8.x4.trans.shared.b16 {%0,%1,%2,%3}, [%4];"
        : "=r"(r[0]), "=r"(r[1]), "=r"(r[2]), "=r"(r[3]) : "r"(addr));
}
__device__ __forceinline__ void mma_bf16(float* d, const uint32_t* a, const uint32_t* b) {
    asm volatile("mma.sync.aligned.m16n8k16.row.col.f32.bf16.bf16.f32 "
        "{%0,%1,%2,%3}, {%4,%5,%6,%7}, {%8,%9}, {%0,%1,%2,%3};"
        : "+f"(d[0]), "+f"(d[1]), "+f"(d[2]), "+f"(d[3])
        : "r"(a[0]), "r"(a[1]), "r"(a[2]), "r"(a[3]), "r"(b[0]), "r"(b[1]));
}
__device__ __forceinline__ void mma_f16(float* d, const uint32_t* a, const uint32_t* b) {
    asm volatile("mma.sync.aligned.m16n8k16.row.col.f32.f16.f16.f32 "
        "{%0,%1,%2,%3}, {%4,%5,%6,%7}, {%8,%9}, {%0,%1,%2,%3};"
        : "+f"(d[0]), "+f"(d[1]), "+f"(d[2]), "+f"(d[3])
        : "r"(a[0]), "r"(a[1]), "r"(a[2]), "r"(a[3]), "r"(b[0]), "r"(b[1]));
}
__device__ __forceinline__ void mma_fp8(float* d, const uint32_t* a, const uint32_t* b) {
    asm volatile("mma.sync.aligned.m16n8k32.row.col.f32.e4m3.e4m3.f32 "
        "{%0,%1,%2,%3}, {%4,%5,%6,%7}, {%8,%9}, {%0,%1,%2,%3};"
        : "+f"(d[0]), "+f"(d[1]), "+f"(d[2]), "+f"(d[3])
        : "r"(a[0]), "r"(a[1]), "r"(a[2]), "r"(a[3]), "r"(b[0]), "r"(b[1]));
}
__device__ __forceinline__ uint32_t pack_bf2(__nv_bfloat16 a, __nv_bfloat16 b) {
    __nv_bfloat162 t = __halves2bfloat162(a, b);
    return *reinterpret_cast<uint32_t*>(&t);
}
__device__ __forceinline__ uint32_t pack_h2(__half a, __half b) {
    __half2 t = __halves2half2(a, b);
    return *reinterpret_cast<uint32_t*>(&t);
}
__device__ __forceinline__ void split_bf(float f, __nv_bfloat16& hi, __nv_bfloat16& lo) {
    hi = __float2bfloat16(f);
    lo = __float2bfloat16(f - __bfloat162float(hi));
}
__device__ __forceinline__ void split_h(float f, __half& hi, __half& lo) {
    hi = __float2half(f);
    lo = __float2half(f - __half2float(hi));
}
__device__ __forceinline__ uint32_t pack_e4m3_4(float f0, float f1, float f2, float f3) {
    uint16_t lo, hi;
    asm("cvt.rn.satfinite.e4m3x2.f32 %0, %1, %2;" : "=h"(lo) : "f"(f1), "f"(f0));
    asm("cvt.rn.satfinite.e4m3x2.f32 %0, %1, %2;" : "=h"(hi) : "f"(f3), "f"(f2));
    return (uint32_t)lo | ((uint32_t)hi << 16);
}

// ================= small kernels =================
__global__ void build_gidx_kernel(const int* __restrict__ src_nodes,
                                  const int* __restrict__ src_idx1,
                                  int* __restrict__ out, int n) {
    int k = blockIdx.x * blockDim.x + threadIdx.x;
    if (k < n) out[k] = src_nodes[src_idx1[k]];
}

__global__ void gather_cat_kernel(const float* __restrict__ src,
                                  const int* __restrict__ idx,
                                  float* __restrict__ cat) {
    int b = blockIdx.x;
    int r = idx[b];
    const float4* s = reinterpret_cast<const float4*>(src + (size_t)r * 512);
    float4* d = reinterpret_cast<float4*>(cat + (size_t)b * 1024 + 512);
    d[threadIdx.x] = s[threadIdx.x];
}

__global__ void gather_cat_split_h_kernel(const float* __restrict__ src,
                                          const int* __restrict__ idx,
                                          const int* __restrict__ map,
                                          __half* __restrict__ chi,
                                          __half* __restrict__ clo) {
    int b = blockIdx.x;
    int r = idx[b];
    if (map) r = map[r];
    float4 v = reinterpret_cast<const float4*>(src + (size_t)r * 512)[threadIdx.x];
    __half h0, h1, h2, h3, l0, l1, l2, l3;
    split_h(v.x, h0, l0); split_h(v.y, h1, l1);
    split_h(v.z, h2, l2); split_h(v.w, h3, l3);
    size_t o = (size_t)b * 1024 + 512;
    reinterpret_cast<uint2*>(chi + o)[threadIdx.x] =
        make_uint2(pack_h2(h0, h1), pack_h2(h2, h3));
    reinterpret_cast<uint2*>(clo + o)[threadIdx.x] =
        make_uint2(pack_h2(l0, l1), pack_h2(l2, l3));
}

__global__ void split_kernel(const float* __restrict__ src,
                             __nv_bfloat16* __restrict__ hi,
                             __nv_bfloat16* __restrict__ lo, int n8) {
    int i = blockIdx.x * blockDim.x + threadIdx.x;
    if (i >= n8) return;
    const float4* s = reinterpret_cast<const float4*>(src) + 2 * (size_t)i;
    float4 a = s[0], b = s[1];
    float f[8] = {a.x, a.y, a.z, a.w, b.x, b.y, b.z, b.w};
    __nv_bfloat16 h[8], l[8];
#pragma unroll
    for (int q = 0; q < 8; ++q) split_bf(f[q], h[q], l[q]);
    reinterpret_cast<uint4*>(hi)[i] = make_uint4(
        pack_bf2(h[0], h[1]), pack_bf2(h[2], h[3]),
        pack_bf2(h[4], h[5]), pack_bf2(h[6], h[7]));
    reinterpret_cast<uint4*>(lo)[i] = make_uint4(
        pack_bf2(l[0], l[1]), pack_bf2(l[2], l[3]),
        pack_bf2(l[4], l[5]), pack_bf2(l[6], l[7]));
}

__global__ void scale_a8_kernel(const float* __restrict__ src,
                                uint8_t* __restrict__ dst, int n8) {
    int i = blockIdx.x * blockDim.x + threadIdx.x;
    if (i >= n8) return;
    const float4* s = reinterpret_cast<const float4*>(src) + 2 * (size_t)i;
    float4 a = s[0], b = s[1];
    uint32_t p0 = pack_e4m3_4(a.x * A_SCALE, a.y * A_SCALE, a.z * A_SCALE, a.w * A_SCALE);
    uint32_t p1 = pack_e4m3_4(b.x * A_SCALE, b.y * A_SCALE, b.z * A_SCALE, b.w * A_SCALE);
    reinterpret_cast<uint2*>(dst)[i] = make_uint2(p0, p1);
}

__global__ void scale_f16_kernel(const float* __restrict__ src,
                                 __half* __restrict__ dst, int n8) {
    int i = blockIdx.x * blockDim.x + threadIdx.x;
    if (i >= n8) return;
    const float4* s = reinterpret_cast<const float4*>(src) + 2 * (size_t)i;
    float4 a = s[0], b = s[1];
    float f[8] = {a.x, a.y, a.z, a.w, b.x, b.y, b.z, b.w};
    __half h[8];
#pragma unroll
    for (int q = 0; q < 8; ++q) h[q] = __float2half(f[q] * A_SCALE);
    reinterpret_cast<uint4*>(dst)[i] = make_uint4(
        pack_h2(h[0], h[1]), pack_h2(h[2], h[3]),
        pack_h2(h[4], h[5]), pack_h2(h[6], h[7]));
}

__global__ void f32_to_f16_kernel(const float* __restrict__ src,
                                  __half* __restrict__ dst, int n4) {
    int i = blockIdx.x * blockDim.x + threadIdx.x;
    if (i >= n4) return;
    float4 v = reinterpret_cast<const float4*>(src)[i];
    reinterpret_cast<uint2*>(dst)[i] =
        make_uint2(pack_h2(__float2half(v.x), __float2half(v.y)),
                   pack_h2(__float2half(v.z), __float2half(v.w)));
}

__global__ void prep_xt8_kernel(const float* __restrict__ features,
                                const int* __restrict__ gidx,
                                uint8_t* __restrict__ xt) {
    __shared__ float tile[128][65];
    const int k0 = blockIdx.x * 128;
    const int n0 = blockIdx.y * 64;
    const int tid = threadIdx.x;
    for (int i = tid; i < 128 * 16; i += 128) {
        int r = i >> 4, c4 = i & 15;
        float4 v = *reinterpret_cast<const float4*>(
            features + (size_t)gidx[k0 + r] * F_DIM + n0 + c4 * 4);
        tile[r][c4 * 4 + 0] = v.x; tile[r][c4 * 4 + 1] = v.y;
        tile[r][c4 * 4 + 2] = v.z; tile[r][c4 * 4 + 3] = v.w;
    }
    __syncthreads();
    for (int i = tid; i < 64 * 32; i += 128) {
        int n = i >> 5, kg = i & 31;
        uint32_t p = pack_e4m3_4(tile[kg * 4 + 0][n], tile[kg * 4 + 1][n],
                                 tile[kg * 4 + 2][n], tile[kg * 4 + 3][n]);
        *reinterpret_cast<uint32_t*>(xt + (size_t)(n0 + n) * S1_CNT + k0 + kg * 4) = p;
    }
}

// ====== GEMM1: fp8, BM=64/BN=128, 512 thr (16 warps 16x32), 4-stage, 2 CTA/SM ======
#define P_A_TILE 8192                 // 64 rows x 128B
#define P_B_TILE 16384                // 128 rows x 128B
#define P_STAGE  (P_A_TILE + P_B_TILE)   // 24KB
#define P_NSTG   4
#define P_SMEM   (P_NSTG * P_STAGE)      // 96KB

__global__ __launch_bounds__(512, 2)
void gemm1_fp8(const uint8_t* __restrict__ A,
               const uint8_t* __restrict__ Bt,
               __half* __restrict__ Chi,
               __half* __restrict__ Clo) {
    constexpr int NCHUNK = S1_CNT / 128;   // 256
    constexpr int LDC = 1024;
    extern __shared__ __align__(128) char smem[];
    const uint32_t sb = smem_u32(smem);
    const int tid = threadIdx.x;
    const int wid = tid >> 5;
    const int lane = tid & 31;
    const int bm = blockIdx.y * 64;
    const int bn = blockIdx.x * 128;
    const int wm = (wid & 3) * 16;         // 4 m-warps of 16 rows
    const int wn = (wid >> 2) * 32;        // 4 n-warps of 32 cols

    float acc[4][4];
#pragma unroll
    for (int n = 0; n < 4; ++n)
#pragma unroll
        for (int j = 0; j < 4; ++j) acc[n][j] = 0.f;

    // persistent cp.async source pointers (A: 1 line/thread, B: 2)
    int rA = tid >> 3, sA = tid & 7;
    int rB1 = (tid + 512) >> 3, sB1 = (tid + 512) & 7;
    const uint8_t* aP  = A + (size_t)(bm + rA) * S1_CNT + sA * 16;
    const uint8_t* bP0 = Bt + (size_t)(bn + rA) * S1_CNT + sA * 16;
    const uint8_t* bP1 = Bt + (size_t)(bn + rB1) * S1_CNT + sB1 * 16;
    const uint32_t dA  = rA * 128 + ((sA ^ (rA & 7)) << 4);
    const uint32_t dB1 = rB1 * 128 + ((sB1 ^ (rB1 & 7)) << 4);

    // hoisted ldsm offsets (stage-invariant)
    const uint32_t mrow = wm + (lane & 15);
    const uint32_t acol = (lane >> 4);
    const uint32_t nrow0 = wn + (lane & 7) + ((lane & 16) >> 1);
    const uint32_t nrow1 = nrow0 + 16;
    const uint32_t bcol = (lane >> 3) & 1;
    uint32_t offA[4], offB[2][4];
#pragma unroll
    for (int kk = 0; kk < 4; ++kk) {
        uint32_t cA = (uint32_t)(kk * 2) + acol;
        uint32_t cB = (uint32_t)(kk * 2) + bcol;
        offA[kk] = mrow * 128 + ((cA ^ (mrow & 7)) << 4);
        offB[0][kk] = P_A_TILE + nrow0 * 128 + ((cB ^ (nrow0 & 7)) << 4);
        offB[1][kk] = P_A_TILE + nrow1 * 128 + ((cB ^ (nrow1 & 7)) << 4);
    }

#define P_LOAD(pred, sbase) do {                                              \
    if (pred) {                                                               \
        CP_ASYNC16((sbase) + dA, aP);                                         \
        CP_ASYNC16((sbase) + P_A_TILE + dA, bP0);                             \
        CP_ASYNC16((sbase) + P_A_TILE + dB1, bP1);                            \
    }                                                                         \
    CP_COMMIT();                                                              \
    aP += 128; bP0 += 128; bP1 += 128;                                        \
} while (0)

    P_LOAD(true, sb + 0 * P_STAGE);
    P_LOAD(true, sb + 1 * P_STAGE);
    P_LOAD(true, sb + 2 * P_STAGE);

    uint32_t cmp_base = sb;
    uint32_t load_base = sb + 3 * P_STAGE;
    const uint32_t smem_end = sb + P_NSTG * P_STAGE;

#pragma unroll 1
    for (int ch = 0; ch < NCHUNK; ++ch) {
        CP_WAIT2();
        __syncthreads();
        P_LOAD(ch + 3 < NCHUNK, load_base);
        load_base += P_STAGE; if (load_base == smem_end) load_base = sb;

        const uint32_t abase = cmp_base;
#pragma unroll
        for (int kk = 0; kk < 4; ++kk) {
            uint32_t ar[4], br[2][4];
            ldsm_x4(ar, abase + offA[kk]);
            ldsm_x4(br[0], abase + offB[0][kk]);
            ldsm_x4(br[1], abase + offB[1][kk]);
#pragma unroll
            for (int j = 0; j < 2; ++j)
#pragma unroll
                for (int h = 0; h < 2; ++h)
                    mma_fp8(acc[j * 2 + h], ar, &br[j][2 * h]);
        }
        cmp_base += P_STAGE; if (cmp_base == smem_end) cmp_base = sb;
    }

    // epilogue: scale + fp16 hi/lo split
#pragma unroll
    for (int half = 0; half < 2; ++half) {
        const int row = bm + wm + half * 8 + (lane >> 2);
#pragma unroll
        for (int n8 = 0; n8 < 4; ++n8) {
            const int col = bn + wn + n8 * 8 + (lane & 3) * 2;
            float v0 = acc[n8][2 * half + 0] * A_INV;
            float v1 = acc[n8][2 * half + 1] * A_INV;
            __half h0, h1, l0, l1;
            split_h(v0, h0, l0);
            split_h(v1, h1, l1);
            size_t o = (size_t)row * LDC + col;
            *reinterpret_cast<uint32_t*>(Chi + o) = pack_h2(h0, h1);
            *reinterpret_cast<uint32_t*>(Clo + o) = pack_h2(l0, l1);
        }
    }
#undef P_LOAD
}

// ================= 2-term fp16 GEMM: C = relu((Ahi+Alo) @ B), K=1024 =================
#define T_A_TILE 16384
#define T_B_TILE 16384
#define T_STAGE  (2 * T_A_TILE + T_B_TILE)
#define T_NSTG   4
#define T_SMEM   (T_NSTG * T_STAGE)

__global__ __launch_bounds__(256, 1)
void gemm_2t_f16(const __half* __restrict__ Ahi,
                 const __half* __restrict__ Alo,
                 const __half* __restrict__ B,
                 float* __restrict__ C,
                 __half* __restrict__ C16) {
    constexpr int NCHUNK = 16;
    constexpr int LDA = 1024, LDB = 512, LDC = 512;
    extern __shared__ __align__(128) char smem[];
    const uint32_t sb = smem_u32(smem);
    const int tid = threadIdx.x;
    const int wid = tid >> 5;
    const int lane = tid & 31;
    const int bm = blockIdx.y * 128;
    const int bn = blockIdx.x * 128;
    const int wm = (wid & 3) * 32;
    const int wn = (wid >> 2) * 64;

    float acc[2][8][4];
#pragma unroll
    for (int m = 0; m < 2; ++m)
#pragma unroll
        for (int n = 0; n < 8; ++n)
#pragma unroll
            for (int j = 0; j < 4; ++j) acc[m][n][j] = 0.f;

#define T_LOAD(ch) do {                                                       \
    if ((ch) < NCHUNK) {                                                      \
        size_t k0 = (size_t)(ch) * 64;                                        \
        uint32_t sa = sb + (uint32_t)((ch) % T_NSTG) * T_STAGE;               \
        uint32_t sB = sa + 2 * T_A_TILE;                                      \
        _Pragma("unroll")                                                     \
        for (int i = 0; i < 4; ++i) {                                         \
            int lin = tid + i * 256;                                          \
            int row = lin >> 3, seg = lin & 7;                                \
            uint32_t d = sa + row * 128 + (((seg ^ (row & 7))) << 4);         \
            CP_ASYNC16(d, Ahi + (size_t)(bm + row) * LDA + k0 + seg * 8);     \
            CP_ASYNC16(d + T_A_TILE, Alo + (size_t)(bm + row) * LDA + k0 + seg * 8); \
        }                                                                     \
        _Pragma("unroll")                                                     \
        for (int i = 0; i < 4; ++i) {                                         \
            int lin = tid + i * 256;                                          \
            int row = lin >> 4, chk = lin & 15;                               \
            uint32_t d = sB + row * 256 + (((chk ^ (row & 7))) << 4);         \
            CP_ASYNC16(d, B + (size_t)(k0 + row) * LDB + bn + chk * 8);       \
        }                                                                     \
    }                                                                         \
    CP_COMMIT();                                                              \
} while (0)

    T_LOAD(0); T_LOAD(1); T_LOAD(2);

    for (int ch = 0; ch < NCHUNK; ++ch) {
        CP_WAIT2();
        __syncthreads();
        T_LOAD(ch + 3);

        const uint32_t abase = sb + (uint32_t)(ch % T_NSTG) * T_STAGE;
        const uint32_t bbase = abase + 2 * T_A_TILE;
#pragma unroll
        for (int kk = 0; kk < 4; ++kk) {
            uint32_t ah[2][4], al[2][4];
#pragma unroll
            for (int m = 0; m < 2; ++m) {
                uint32_t r = wm + m * 16 + (lane & 15);
                uint32_t c = kk * 2 + (lane >> 4);
                uint32_t ad = abase + r * 128 + ((c ^ (r & 7)) << 4);
                ldsm_x4(ah[m], ad);
                ldsm_x4(al[m], ad + T_A_TILE);
            }
            uint32_t bh[4][4];
#pragma unroll
            for (int j = 0; j < 4; ++j) {
                uint32_t krow = kk * 16 + (lane & 15);
                uint32_t chk = (uint32_t)(wn >> 3) + j * 2 + (lane >> 4);
                ldsm_x4_t(bh[j], bbase + krow * 256 + ((chk ^ (krow & 7)) << 4));
            }
#pragma unroll
            for (int m = 0; m < 2; ++m)
#pragma unroll
                for (int j = 0; j < 4; ++j)
#pragma unroll
                    for (int h = 0; h < 2; ++h) {
                        const int n8 = j * 2 + h;
                        mma_f16(acc[m][n8], ah[m], &bh[j][2 * h]);
                        mma_f16(acc[m][n8], al[m], &bh[j][2 * h]);
                    }
        }
        __syncthreads();
    }

#pragma unroll
    for (int m = 0; m < 2; ++m) {
        const int row = bm + wm + m * 16 + (lane >> 2);
#pragma unroll
        for (int n8 = 0; n8 < 8; ++n8) {
            const int col = bn + wn + n8 * 8 + (lane & 3) * 2;
            float2 v0 = make_float2(fmaxf(acc[m][n8][0], 0.f), fmaxf(acc[m][n8][1], 0.f));
            float2 v1 = make_float2(fmaxf(acc[m][n8][2], 0.f), fmaxf(acc[m][n8][3], 0.f));
            *reinterpret_cast<float2*>(C + (size_t)row * LDC + col) = v0;
            *reinterpret_cast<float2*>(C + (size_t)(row + 8) * LDC + col) = v1;
            if (C16) {
                *reinterpret_cast<uint32_t*>(C16 + (size_t)row * LDC + col) =
                    pack_h2(__float2half(v0.x), __float2half(v0.y));
                *reinterpret_cast<uint32_t*>(C16 + (size_t)(row + 8) * LDC + col) =
                    pack_h2(__float2half(v1.x), __float2half(v1.y));
            }
        }
    }
#undef T_LOAD
}

// ================= GEMM2 (agg2): fp16 single, gathered B =================
#define Q_A_TILE 16384
#define Q_B_TILE 16384
#define Q_STAGE  (Q_A_TILE + Q_B_TILE)
#define Q_NSTG   6
#define Q_SMEM   (Q_NSTG * Q_STAGE)

__global__ __launch_bounds__(256, 1)
void gemm2_f16(const __half* __restrict__ A,
               const __half* __restrict__ B,
               const int* __restrict__ gidx,
               float* __restrict__ C) {
    constexpr int NCHUNK = S2_CNT / 64;
    constexpr int LDA = S2_CNT, LDB = D_DIM, LDC = 1024;
    extern __shared__ __align__(128) char smem[];
    const uint32_t sb = smem_u32(smem);
    const int tid = threadIdx.x;
    const int wid = tid >> 5;
    const int lane = tid & 31;
    const int bm = blockIdx.y * 128;
    const int bn = blockIdx.x * 128;
    const int wm = (wid & 3) * 32;
    const int wn = (wid >> 2) * 64;

    float acc[2][8][4];
#pragma unroll
    for (int m = 0; m < 2; ++m)
#pragma unroll
        for (int n = 0; n < 8; ++n)
#pragma unroll
            for (int j = 0; j < 4; ++j) acc[m][n][j] = 0.f;

#define Q_LOAD(ch) do {                                                       \
    if ((ch) < NCHUNK) {                                                      \
        size_t k0 = (size_t)(ch) * 64;                                        \
        uint32_t sa = sb + (uint32_t)((ch) % Q_NSTG) * Q_STAGE;               \
        uint32_t sB = sa + Q_A_TILE;                                          \
        _Pragma("unroll")                                                     \
        for (int i = 0; i < 4; ++i) {                                         \
            int lin = tid + i * 256;                                          \
            int row = lin >> 3, seg = lin & 7;                                \
            uint32_t d = sa + row * 128 + (((seg ^ (row & 7))) << 4);         \
            CP_ASYNC16(d, A + (size_t)(bm + row) * LDA + k0 + seg * 8);       \
        }                                                                     \
        _Pragma("unroll")                                                     \
        for (int i = 0; i < 4; ++i) {                                         \
            int lin = tid + i * 256;                                          \
            int row = lin >> 4, chk = lin & 15;                               \
            int g = gidx[k0 + row];                                           \
            uint32_t d = sB + row * 256 + (((chk ^ (row & 7))) << 4);         \
            CP_ASYNC16(d, B + (size_t)g * LDB + bn + chk * 8);                \
        }                                                                     \
    }                                                                         \
    CP_COMMIT();                                                              \
} while (0)

    Q_LOAD(0); Q_LOAD(1); Q_LOAD(2); Q_LOAD(3); Q_LOAD(4);

    for (int ch = 0; ch < NCHUNK; ++ch) {
        CP_WAIT4();
        __syncthreads();
        Q_LOAD(ch + 5);

        const uint32_t abase = sb + (uint32_t)(ch % Q_NSTG) * Q_STAGE;
        const uint32_t bbase = abase + Q_A_TILE;
#pragma unroll
        for (int kk = 0; kk < 4; ++kk) {
            uint32_t ah[2][4];
#pragma unroll
            for (int m = 0; m < 2; ++m) {
                uint32_t r = wm + m * 16 + (lane & 15);
                uint32_t c = kk * 2 + (lane >> 4);
                ldsm_x4(ah[m], abase + r * 128 + ((c ^ (r & 7)) << 4));
            }
            uint32_t bh[4][4];
#pragma unroll
            for (int j = 0; j < 4; ++j) {
                uint32_t krow = kk * 16 + (lane & 15);
                uint32_t chk = (uint32_t)(wn >> 3) + j * 2 + (lane >> 4);
                ldsm_x4_t(bh[j], bbase + krow * 256 + ((chk ^ (krow & 7)) << 4));
            }
#pragma unroll
            for (int m = 0; m < 2; ++m)
#pragma unroll
                for (int j = 0; j < 4; ++j)
#pragma unroll
                    for (int h = 0; h < 2; ++h)
                        mma_f16(acc[m][j * 2 + h], ah[m], &bh[j][2 * h]);
        }
        __syncthreads();
    }

#pragma unroll
    for (int m = 0; m < 2; ++m) {
        const int row = bm + wm + m * 16 + (lane >> 2);
#pragma unroll
        for (int n8 = 0; n8 < 8; ++n8) {
            const int col = bn + wn + n8 * 8 + (lane & 3) * 2;
            *reinterpret_cast<float2*>(C + (size_t)row * LDC + col) =
                make_float2(acc[m][n8][0] * A_INV, acc[m][n8][1] * A_INV);
            *reinterpret_cast<float2*>(C + (size_t)(row + 8) * LDC + col) =
                make_float2(acc[m][n8][2] * A_INV, acc[m][n8][3] * A_INV);
        }
    }
#undef Q_LOAD
}

// ================= bf16 3-term GEMM (layer-2 h2) =================
#define A_TILE_B 16384
#define B_TILE_B 16384
#define STAGE_B  (2 * A_TILE_B + 2 * B_TILE_B)
#define GSMEM    (3 * STAGE_B)

__global__ __launch_bounds__(256, 1)
void gemm_hmma3(const __nv_bfloat16* __restrict__ Ahi,
                const __nv_bfloat16* __restrict__ Alo,
                const __nv_bfloat16* __restrict__ Bhi,
                const __nv_bfloat16* __restrict__ Blo,
                float* __restrict__ C) {
    constexpr int NCHUNK = 16;
    constexpr int LDA = 1024, LDB = 512, LDC = 512;
    extern __shared__ __align__(128) char smem[];
    const uint32_t sb = smem_u32(smem);
    const int tid = threadIdx.x;
    const int wid = tid >> 5;
    const int lane = tid & 31;
    const int bm = blockIdx.y * 128;
    const int bn = blockIdx.x * 128;
    const int wm = (wid & 3) * 32;
    const int wn = (wid >> 2) * 64;

    float acc[2][8][4];
#pragma unroll
    for (int m = 0; m < 2; ++m)
#pragma unroll
        for (int n = 0; n < 8; ++n)
#pragma unroll
            for (int j = 0; j < 4; ++j) acc[m][n][j] = 0.f;

#define G_LOAD(ch, stg) do {                                                  \
    if ((ch) < NCHUNK) {                                                      \
        size_t k0 = (size_t)(ch) * 64;                                        \
        uint32_t sa = sb + (uint32_t)(stg) * STAGE_B;                         \
        uint32_t sB = sa + 2 * A_TILE_B;                                      \
        _Pragma("unroll")                                                     \
        for (int i = 0; i < 4; ++i) {                                         \
            int lin = tid + i * 256;                                          \
            int row = lin >> 3, seg = lin & 7;                                \
            uint32_t d = sa + row * 128 + (((seg ^ (row & 7))) << 4);         \
            CP_ASYNC16(d, Ahi + (size_t)(bm + row) * LDA + k0 + seg * 8);     \
            CP_ASYNC16(d + A_TILE_B, Alo + (size_t)(bm + row) * LDA + k0 + seg * 8); \
        }                                                                     \
        _Pragma("unroll")                                                     \
        for (int i = 0; i < 4; ++i) {                                         \
            int lin = tid + i * 256;                                          \
            int row = lin >> 4, chk = lin & 15;                               \
            uint32_t d = sB + row * 256 + (((chk ^ (row & 7))) << 4);         \
            CP_ASYNC16(d, Bhi + (size_t)(k0 + row) * LDB + bn + chk * 8);     \
            CP_ASYNC16(d + B_TILE_B, Blo + (size_t)(k0 + row) * LDB + bn + chk * 8); \
        }                                                                     \
    }                                                                         \
    CP_COMMIT();                                                              \
} while (0)

    G_LOAD(0, 0);
    G_LOAD(1, 1);

    int stg = 0;
    for (int ch = 0; ch < NCHUNK; ++ch) {
        CP_WAIT1();
        __syncthreads();
        G_LOAD(ch + 2, (stg + 2 >= 3) ? (stg - 1) : (stg + 2));

        const uint32_t abase = sb + (uint32_t)stg * STAGE_B;
        const uint32_t bbase = abase + 2 * A_TILE_B;
#pragma unroll
        for (int kk = 0; kk < 4; ++kk) {
            uint32_t ah[2][4], al[2][4];
#pragma unroll
            for (int m = 0; m < 2; ++m) {
                uint32_t r = wm + m * 16 + (lane & 15);
                uint32_t c = kk * 2 + (lane >> 4);
                uint32_t ad = abase + r * 128 + ((c ^ (r & 7)) << 4);
                ldsm_x4(ah[m], ad);
                ldsm_x4(al[m], ad + A_TILE_B);
            }
            uint32_t bh[4][4], bl[4][4];
#pragma unroll
            for (int j = 0; j < 4; ++j) {
                uint32_t krow = kk * 16 + (lane & 15);
                uint32_t chk = (uint32_t)(wn >> 3) + j * 2 + (lane >> 4);
                uint32_t bd = bbase + krow * 256 + ((chk ^ (krow & 7)) << 4);
                ldsm_x4_t(bh[j], bd);
                ldsm_x4_t(bl[j], bd + B_TILE_B);
            }
#pragma unroll
            for (int m = 0; m < 2; ++m)
#pragma unroll
                for (int j = 0; j < 4; ++j)
#pragma unroll
                    for (int h = 0; h < 2; ++h) {
                        const int n8 = j * 2 + h;
                        mma_bf16(acc[m][n8], ah[m], &bh[j][2 * h]);
                        mma_bf16(acc[m][n8], ah[m], &bl[j][2 * h]);
                        mma_bf16(acc[m][n8], al[m], &bh[j][2 * h]);
                    }
        }
        stg = (stg + 1 == 3) ? 0 : stg + 1;
    }

#pragma unroll
    for (int m = 0; m < 2; ++m) {
        const int row = bm + wm + m * 16 + (lane >> 2);
#pragma unroll
        for (int n8 = 0; n8 < 8; ++n8) {
            const int col = bn + wn + n8 * 8 + (lane & 3) * 2;
            *reinterpret_cast<float2*>(C + (size_t)row * LDC + col) =
                make_float2(fmaxf(acc[m][n8][0], 0.f), fmaxf(acc[m][n8][1], 0.f));
            *reinterpret_cast<float2*>(C + (size_t)(row + 8) * LDC + col) =
                make_float2(fmaxf(acc[m][n8][2], 0.f), fmaxf(acc[m][n8][3], 0.f));
        }
    }
#undef G_LOAD
}

// ================= classifier + softmax =================
__global__ void cls_softmax_kernel(const float* __restrict__ h2,
                                   const float* __restrict__ wc,
                                   float* __restrict__ out) {
    __shared__ float sh[D_DIM];
    __shared__ float red[C_DIM];
    const int b = blockIdx.x;
    const int c = threadIdx.x;
    for (int i = c; i < D_DIM; i += C_DIM) sh[i] = h2[(size_t)b * D_DIM + i];
    __syncthreads();
    float acc = 0.f;
#pragma unroll 8
    for (int k = 0; k < D_DIM; ++k)
        acc = fmaf(sh[k], wc[(size_t)k * C_DIM + c], acc);
    red[c] = acc;
    __syncthreads();
    for (int s = C_DIM / 2; s > 0; s >>= 1) {
        if (c < s) red[c] = fmaxf(red[c], red[c + s]);
        __syncthreads();
    }
    float mx = red[0];
    __syncthreads();
    float e = expf(acc - mx);
    red[c] = e;
    __syncthreads();
    for (int s = C_DIM / 2; s > 0; s >>= 1) {
        if (c < s) red[c] += red[c + s];
        __syncthreads();
    }
    out[(size_t)b * C_DIM + c] = e / red[0];
}

// ================= launch =================
extern "C" void kernel_launch(void* const* d_in, const int* in_sizes, int n_in,
                              void* d_out, int out_size) {
    const float* features  = (const float*)d_in[0];
    const int*   src_nodes = (const int*)d_in[1];
    const int*   dst_idx1  = (const int*)d_in[2];
    const int*   src_idx1  = (const int*)d_in[3];
    const float* dif_mat1  = (const float*)d_in[4];
    const int*   dst_idx2  = (const int*)d_in[5];
    const int*   src_idx2  = (const int*)d_in[6];
    const float* dif_mat2  = (const float*)d_in[7];
    const float* w1        = (const float*)d_in[8];
    const float* w2        = (const float*)d_in[9];
    const float* w_cls     = (const float*)d_in[10];
    float* out = (float*)d_out;

    float *h1, *cat2, *h2;
    int* gidx1;
    uint8_t *a8, *xt8;
    __half *a2, *h1f16, *c1hi, *c1lo, *w1h;
    __nv_bfloat16 *c2hi, *c2lo, *w2hi, *w2lo;
    cudaGetSymbolAddress((void**)&h1,    g_h1);
    cudaGetSymbolAddress((void**)&cat2,  g_cat2);
    cudaGetSymbolAddress((void**)&h2,    g_h2);
    cudaGetSymbolAddress((void**)&gidx1, g_gidx1);
    cudaGetSymbolAddress((void**)&a8,    g_a8);
    cudaGetSymbolAddress((void**)&xt8,   g_xt8);
    cudaGetSymbolAddress((void**)&a2,    g_a2);
    cudaGetSymbolAddress((void**)&h1f16, g_h1f16);
    cudaGetSymbolAddress((void**)&c1hi,  g_c1hi);
    cudaGetSymbolAddress((void**)&c1lo,  g_c1lo);
    cudaGetSymbolAddress((void**)&w1h,   g_w1h);
    cudaGetSymbolAddress((void**)&c2hi,  g_c2hi);
    cudaGetSymbolAddress((void**)&c2lo,  g_c2lo);
    cudaGetSymbolAddress((void**)&w2hi,  g_w2hi);
    cudaGetSymbolAddress((void**)&w2lo,  g_w2lo);

    cudaFuncSetAttribute((const void*)gemm1_fp8,
                         cudaFuncAttributeMaxDynamicSharedMemorySize, P_SMEM);
    cudaFuncSetAttribute((const void*)gemm_2t_f16,
                         cudaFuncAttributeMaxDynamicSharedMemorySize, T_SMEM);
    cudaFuncSetAttribute((const void*)gemm2_f16,
                         cudaFuncAttributeMaxDynamicSharedMemorySize, Q_SMEM);
    cudaFuncSetAttribute((const void*)gemm_hmma3,
                         cudaFuncAttributeMaxDynamicSharedMemorySize, GSMEM);

    // launches 1-3: prep so gemm1 is the 4th launch (ncu -s 5 -c 1 lands on it)
    {
        int n8 = (B1_CNT * S1_CNT) / 8;
        scale_a8_kernel<<<n8 / 256, 256>>>(dif_mat1, a8, n8);
    }
    build_gidx_kernel<<<(S1_CNT + 255) / 256, 256>>>(src_nodes, src_idx1, gidx1, S1_CNT);
    prep_xt8_kernel<<<dim3(S1_CNT / 128, F_DIM / 64), 128>>>(features, gidx1, xt8);

    // 4: agg1 -> c1hi/c1lo[:, 0:512] (fp8, BM=64, 2 CTAs/SM)
    gemm1_fp8<<<dim3(F_DIM / 128, B1_CNT / 64), 512, P_SMEM>>>(a8, xt8, c1hi, c1lo);

    gather_cat_split_h_kernel<<<B1_CNT, 128>>>(features, dst_idx1, src_nodes, c1hi, c1lo);
    f32_to_f16_kernel<<<(1024 * D_DIM / 4) / 256, 256>>>(w1, w1h, 1024 * D_DIM / 4);

    gemm_2t_f16<<<dim3(D_DIM / 128, B1_CNT / 128), 256, T_SMEM>>>(c1hi, c1lo, w1h, h1, h1f16);

    {
        int a8n = (B2_CNT * S2_CNT) / 8;
        scale_f16_kernel<<<(a8n + 255) / 256, 256>>>(dif_mat2, a2, a8n);
    }
    gather_cat_kernel<<<B2_CNT, 128>>>(h1, dst_idx2, cat2);
    gemm2_f16<<<dim3(D_DIM / 128, B2_CNT / 128), 256, Q_SMEM>>>(a2, h1f16, src_idx2, cat2);
    {
        int n8 = (B2_CNT * 1024) / 8;
        split_kernel<<<(n8 + 255) / 256, 256>>>(cat2, c2hi, c2lo, n8);
        int m8 = (1024 * D_DIM) / 8;
        split_kernel<<<m8 / 256, 256>>>(w2, w2hi, w2lo, m8);
    }
    gemm_hmma3<<<dim3(D_DIM / 128, B2_CNT / 128), 256, GSMEM>>>(c2hi, c2lo, w2hi, w2lo, h2);

    cls_softmax_kernel<<<B2_CNT, C_DIM>>>(h2, w_cls, out);
}

// round 14
// speedup vs baseline: 2.0262x; 1.0753x over previous
#include <cuda_runtime.h>
#include <cuda_fp16.h>
#include <cstdint>
#include <math.h>

// ---------------- problem constants ----------------
#define V_NODES 100000
#define F_DIM   512
#define D_DIM   512
#define C_DIM   128
#define N1_CNT  36864
#define S1_CNT  32768
#define B1_CNT  4096
#define S2_CNT  3584
#define B2_CNT  512

#define A_SCALE 32768.0f
#define A_INV   (1.0f / 32768.0f)

// ---------------- scratch (device globals) ----------------
__device__ float g_h1  [B1_CNT * D_DIM];
__device__ float g_h2  [B2_CNT * D_DIM];
__device__ uint8_t g_a8 [(size_t)B1_CNT * S1_CNT];
__device__ uint8_t g_xt8[(size_t)F_DIM * S1_CNT];
__device__ __half  g_a2 [(size_t)B2_CNT * S2_CNT];
__device__ __half  g_h1f16[(size_t)B1_CNT * D_DIM];
__device__ __half  g_c1 [(size_t)B1_CNT * 1024];   // cat1 fp16 [agg | dst]
__device__ __half  g_c2 [(size_t)B2_CNT * 1024];   // cat2 fp16
__device__ __half  g_w1h[1024 * D_DIM];
__device__ __half  g_w2h[1024 * D_DIM];

typedef unsigned long long u64t;

// ================= helpers =================
__device__ __forceinline__ uint32_t smem_u32(const void* p) {
    uint32_t a;
    asm("{ .reg .u64 t; cvta.to.shared.u64 t, %1; cvt.u32.u64 %0, t; }" : "=r"(a) : "l"(p));
    return a;
}
#define CP_ASYNC16(sm, gm) asm volatile("cp.async.cg.shared.global [%0], [%1], 16;" :: "r"(sm), "l"(gm) : "memory")
#define CP_COMMIT()        asm volatile("cp.async.commit_group;" ::: "memory")
#define CP_WAIT2()         asm volatile("cp.async.wait_group 2;" ::: "memory")
#define CP_WAIT3()         asm volatile("cp.async.wait_group 3;" ::: "memory")
#define CP_WAIT4()         asm volatile("cp.async.wait_group 4;" ::: "memory")

__device__ __forceinline__ void ldsm_x4(uint32_t* r, uint32_t addr) {
    asm volatile("ldmatrix.sync.aligned.m8n8.x4.shared.b16 {%0,%1,%2,%3}, [%4];"
        : "=r"(r[0]), "=r"(r[1]), "=r"(r[2]), "=r"(r[3]) : "r"(addr));
}
__device__ __forceinline__ void ldsm_x4_t(uint32_t* r, uint32_t addr) {
    asm volatile("ldmatrix.sync.aligned.m8n8.x4.trans.shared.b16 {%0,%1,%2,%3}, [%4];"
        : "=r"(r[0]), "=r"(r[1]), "=r"(r[2]), "=r"(r[3]) : "r"(addr));
}
__device__ __forceinline__ void mma_f16(float* d, const uint32_t* a, const uint32_t* b) {
    asm volatile("mma.sync.aligned.m16n8k16.row.col.f32.f16.f16.f32 "
        "{%0,%1,%2,%3}, {%4,%5,%6,%7}, {%8,%9}, {%0,%1,%2,%3};"
        : "+f"(d[0]), "+f"(d[1]), "+f"(d[2]), "+f"(d[3])
        : "r"(a[0]), "r"(a[1]), "r"(a[2]), "r"(a[3]), "r"(b[0]), "r"(b[1]));
}
__device__ __forceinline__ void mma_fp8(float* d, const uint32_t* a, const uint32_t* b) {
    asm volatile("mma.sync.aligned.m16n8k32.row.col.f32.e4m3.e4m3.f32 "
        "{%0,%1,%2,%3}, {%4,%5,%6,%7}, {%8,%9}, {%0,%1,%2,%3};"
        : "+f"(d[0]), "+f"(d[1]), "+f"(d[2]), "+f"(d[3])
        : "r"(a[0]), "r"(a[1]), "r"(a[2]), "r"(a[3]), "r"(b[0]), "r"(b[1]));
}
__device__ __forceinline__ uint32_t pack_h2(__half a, __half b) {
    __half2 t = __halves2half2(a, b);
    return *reinterpret_cast<uint32_t*>(&t);
}
__device__ __forceinline__ uint32_t pack_e4m3_4(float f0, float f1, float f2, float f3) {
    uint16_t lo, hi;
    asm("cvt.rn.satfinite.e4m3x2.f32 %0, %1, %2;" : "=h"(lo) : "f"(f1), "f"(f0));
    asm("cvt.rn.satfinite.e4m3x2.f32 %0, %1, %2;" : "=h"(hi) : "f"(f3), "f"(f2));
    return (uint32_t)lo | ((uint32_t)hi << 16);
}

// ================= small kernels =================
// layer-1 dst gather: c1 cols 512:1024 <- f16(features[src_nodes[dst_idx1[b]]])
__global__ void gather_c1_kernel(const float* __restrict__ features,
                                 const int* __restrict__ dst_idx1,
                                 const int* __restrict__ src_nodes,
                                 __half* __restrict__ c1) {
    int b = blockIdx.x;
    int r = src_nodes[dst_idx1[b]];
    float4 v = reinterpret_cast<const float4*>(features + (size_t)r * 512)[threadIdx.x];
    reinterpret_cast<uint2*>(c1 + (size_t)b * 1024 + 512)[threadIdx.x] =
        make_uint2(pack_h2(__float2half(v.x), __float2half(v.y)),
                   pack_h2(__float2half(v.z), __float2half(v.w)));
}

// layer-2 dst gather: c2 cols 512:1024 <- h1f16[dst_idx2[b]] (fp16 copy)
__global__ void gather_c2_kernel(const __half* __restrict__ h1f16,
                                 const int* __restrict__ dst_idx2,
                                 __half* __restrict__ c2) {
    int b = blockIdx.x;
    int r = dst_idx2[b];
    reinterpret_cast<uint2*>(c2 + (size_t)b * 1024 + 512)[threadIdx.x] =
        reinterpret_cast<const uint2*>(h1f16 + (size_t)r * 512)[threadIdx.x];
}

// fp32 * 2^15 -> e4m3 (8/thread)
__global__ void scale_a8_kernel(const float* __restrict__ src,
                                uint8_t* __restrict__ dst, int n8) {
    int i = blockIdx.x * blockDim.x + threadIdx.x;
    if (i >= n8) return;
    const float4* s = reinterpret_cast<const float4*>(src) + 2 * (size_t)i;
    float4 a = s[0], b = s[1];
    uint32_t p0 = pack_e4m3_4(a.x * A_SCALE, a.y * A_SCALE, a.z * A_SCALE, a.w * A_SCALE);
    uint32_t p1 = pack_e4m3_4(b.x * A_SCALE, b.y * A_SCALE, b.z * A_SCALE, b.w * A_SCALE);
    reinterpret_cast<uint2*>(dst)[i] = make_uint2(p0, p1);
}

// fp32 * 2^15 -> fp16 (8/thread)
__global__ void scale_f16_kernel(const float* __restrict__ src,
                                 __half* __restrict__ dst, int n8) {
    int i = blockIdx.x * blockDim.x + threadIdx.x;
    if (i >= n8) return;
    const float4* s = reinterpret_cast<const float4*>(src) + 2 * (size_t)i;
    float4 a = s[0], b = s[1];
    float f[8] = {a.x, a.y, a.z, a.w, b.x, b.y, b.z, b.w};
    __half h[8];
#pragma unroll
    for (int q = 0; q < 8; ++q) h[q] = __float2half(f[q] * A_SCALE);
    reinterpret_cast<uint4*>(dst)[i] = make_uint4(
        pack_h2(h[0], h[1]), pack_h2(h[2], h[3]),
        pack_h2(h[4], h[5]), pack_h2(h[6], h[7]));
}

// fp32 -> fp16 (4/thread)
__global__ void f32_to_f16_kernel(const float* __restrict__ src,
                                  __half* __restrict__ dst, int n4) {
    int i = blockIdx.x * blockDim.x + threadIdx.x;
    if (i >= n4) return;
    float4 v = reinterpret_cast<const float4*>(src)[i];
    reinterpret_cast<uint2*>(dst)[i] =
        make_uint2(pack_h2(__float2half(v.x), __float2half(v.y)),
                   pack_h2(__float2half(v.z), __float2half(v.w)));
}

// gather (composed index inline) + transpose + e4m3
__global__ void prep_xt8_kernel(const float* __restrict__ features,
                                const int* __restrict__ src_idx1,
                                const int* __restrict__ src_nodes,
                                uint8_t* __restrict__ xt) {
    __shared__ float tile[128][65];
    const int k0 = blockIdx.x * 128;
    const int n0 = blockIdx.y * 64;
    const int tid = threadIdx.x;
    for (int i = tid; i < 128 * 16; i += 128) {
        int r = i >> 4, c4 = i & 15;
        int row = src_nodes[src_idx1[k0 + r]];
        float4 v = *reinterpret_cast<const float4*>(
            features + (size_t)row * F_DIM + n0 + c4 * 4);
        tile[r][c4 * 4 + 0] = v.x; tile[r][c4 * 4 + 1] = v.y;
        tile[r][c4 * 4 + 2] = v.z; tile[r][c4 * 4 + 3] = v.w;
    }
    __syncthreads();
    for (int i = tid; i < 64 * 32; i += 128) {
        int n = i >> 5, kg = i & 31;
        uint32_t p = pack_e4m3_4(tile[kg * 4 + 0][n], tile[kg * 4 + 1][n],
                                 tile[kg * 4 + 2][n], tile[kg * 4 + 3][n]);
        *reinterpret_cast<uint32_t*>(xt + (size_t)(n0 + n) * S1_CNT + k0 + kg * 4) = p;
    }
}

// ===== GEMM1: fp8, 512 thr, 5-stage, hoisted offsets (R11 config), f16 epilogue =====
#define P_A_TILE 16384
#define P_B_TILE 16384
#define P_STAGE  (P_A_TILE + P_B_TILE)   // 32KB
#define P_NSTG   5
#define P_SMEM   (P_NSTG * P_STAGE)      // 160KB

__global__ __launch_bounds__(512, 1)
void gemm1_fp8(const uint8_t* __restrict__ A,
               const uint8_t* __restrict__ Bt,
               __half* __restrict__ C) {
    constexpr int NCHUNK = S1_CNT / 128;   // 256
    constexpr int LDC = 1024;
    extern __shared__ __align__(128) char smem[];
    const uint32_t sb = smem_u32(smem);
    const int tid = threadIdx.x;
    const int wid = tid >> 5;
    const int lane = tid & 31;
    const int bm = blockIdx.y * 128;
    const int bn = blockIdx.x * 128;
    const int wm = (wid & 3) * 32;
    const int wn = (wid >> 2) * 32;

    float acc[2][4][4];
#pragma unroll
    for (int m = 0; m < 2; ++m)
#pragma unroll
        for (int n = 0; n < 4; ++n)
#pragma unroll
            for (int j = 0; j < 4; ++j) acc[m][n][j] = 0.f;

    int rA0 = tid >> 3,          sA0 = tid & 7;
    int rA1 = (tid + 512) >> 3,  sA1 = (tid + 512) & 7;
    const uint8_t* aP0 = A + (size_t)(bm + rA0) * S1_CNT + sA0 * 16;
    const uint8_t* aP1 = A + (size_t)(bm + rA1) * S1_CNT + sA1 * 16;
    const uint8_t* bP0 = Bt + (size_t)(bn + rA0) * S1_CNT + sA0 * 16;
    const uint8_t* bP1 = Bt + (size_t)(bn + rA1) * S1_CNT + sA1 * 16;
    const uint32_t dA0 = rA0 * 128 + ((sA0 ^ (rA0 & 7)) << 4);
    const uint32_t dA1 = rA1 * 128 + ((sA1 ^ (rA1 & 7)) << 4);

    const uint32_t mrow0 = wm + (lane & 15);
    const uint32_t mrow1 = mrow0 + 16;
    const uint32_t acol  = (lane >> 4);
    const uint32_t nrow0 = wn + (lane & 7) + ((lane & 16) >> 1);
    const uint32_t nrow1 = nrow0 + 16;
    const uint32_t bcol  = (lane >> 3) & 1;
    uint32_t offA[2][4], offB[2][4];
#pragma unroll
    for (int kk = 0; kk < 4; ++kk) {
        uint32_t cA = (uint32_t)(kk * 2) + acol;
        uint32_t cB = (uint32_t)(kk * 2) + bcol;
        offA[0][kk] = mrow0 * 128 + ((cA ^ (mrow0 & 7)) << 4);
        offA[1][kk] = mrow1 * 128 + ((cA ^ (mrow1 & 7)) << 4);
        offB[0][kk] = P_A_TILE + nrow0 * 128 + ((cB ^ (nrow0 & 7)) << 4);
        offB[1][kk] = P_A_TILE + nrow1 * 128 + ((cB ^ (nrow1 & 7)) << 4);
    }

#define P_LOAD(pred, sbase) do {                                              \
    if (pred) {                                                               \
        CP_ASYNC16((sbase) + dA0, aP0);                                       \
        CP_ASYNC16((sbase) + dA1, aP1);                                       \
        CP_ASYNC16((sbase) + P_A_TILE + dA0, bP0);                            \
        CP_ASYNC16((sbase) + P_A_TILE + dA1, bP1);                            \
    }                                                                         \
    CP_COMMIT();                                                              \
    aP0 += 128; aP1 += 128; bP0 += 128; bP1 += 128;                           \
} while (0)

    P_LOAD(true, sb + 0 * P_STAGE);
    P_LOAD(true, sb + 1 * P_STAGE);
    P_LOAD(true, sb + 2 * P_STAGE);
    P_LOAD(true, sb + 3 * P_STAGE);

    uint32_t cmp_base = sb;
    uint32_t load_base = sb + 4 * P_STAGE;
    const uint32_t smem_end = sb + P_NSTG * P_STAGE;

#pragma unroll 1
    for (int ch = 0; ch < NCHUNK; ++ch) {
        CP_WAIT3();
        __syncthreads();
        P_LOAD(ch + 4 < NCHUNK, load_base);
        load_base += P_STAGE; if (load_base == smem_end) load_base = sb;

        const uint32_t abase = cmp_base;
#pragma unroll
        for (int kk = 0; kk < 4; ++kk) {
            uint32_t ar[2][4], br[2][4];
            ldsm_x4(ar[0], abase + offA[0][kk]);
            ldsm_x4(ar[1], abase + offA[1][kk]);
            ldsm_x4(br[0], abase + offB[0][kk]);
            ldsm_x4(br[1], abase + offB[1][kk]);
#pragma unroll
            for (int m = 0; m < 2; ++m)
#pragma unroll
                for (int j = 0; j < 2; ++j)
#pragma unroll
                    for (int h = 0; h < 2; ++h)
                        mma_fp8(acc[m][j * 2 + h], ar[m], &br[j][2 * h]);
        }
        cmp_base += P_STAGE; if (cmp_base == smem_end) cmp_base = sb;
    }

    // epilogue: scale -> single fp16
#pragma unroll
    for (int m = 0; m < 2; ++m) {
#pragma unroll
        for (int half = 0; half < 2; ++half) {
            const int row = bm + wm + m * 16 + half * 8 + (lane >> 2);
#pragma unroll
            for (int n8 = 0; n8 < 4; ++n8) {
                const int col = bn + wn + n8 * 8 + (lane & 3) * 2;
                float v0 = acc[m][n8][2 * half + 0] * A_INV;
                float v1 = acc[m][n8][2 * half + 1] * A_INV;
                *reinterpret_cast<uint32_t*>(C + (size_t)row * LDC + col) =
                    pack_h2(__float2half(v0), __float2half(v1));
            }
        }
    }
#undef P_LOAD
}

// ===== single-term fp16 GEMM: C = relu(A @ B), A[M,1024] f16, B[1024,512] f16 =====
#define T_A_TILE 16384
#define T_B_TILE 16384
#define T_STAGE  (T_A_TILE + T_B_TILE)
#define T_NSTG   4
#define T_SMEM   (T_NSTG * T_STAGE)

__global__ __launch_bounds__(256, 1)
void gemm_1t_f16(const __half* __restrict__ A,
                 const __half* __restrict__ B,
                 float* __restrict__ C,
                 __half* __restrict__ C16) {
    constexpr int NCHUNK = 16;
    constexpr int LDA = 1024, LDB = 512, LDC = 512;
    extern __shared__ __align__(128) char smem[];
    const uint32_t sb = smem_u32(smem);
    const int tid = threadIdx.x;
    const int wid = tid >> 5;
    const int lane = tid & 31;
    const int bm = blockIdx.y * 128;
    const int bn = blockIdx.x * 128;
    const int wm = (wid & 3) * 32;
    const int wn = (wid >> 2) * 64;

    float acc[2][8][4];
#pragma unroll
    for (int m = 0; m < 2; ++m)
#pragma unroll
        for (int n = 0; n < 8; ++n)
#pragma unroll
            for (int j = 0; j < 4; ++j) acc[m][n][j] = 0.f;

#define T_LOAD(ch) do {                                                       \
    if ((ch) < NCHUNK) {                                                      \
        size_t k0 = (size_t)(ch) * 64;                                        \
        uint32_t sa = sb + (uint32_t)((ch) % T_NSTG) * T_STAGE;               \
        uint32_t sB = sa + T_A_TILE;                                          \
        _Pragma("unroll")                                                     \
        for (int i = 0; i < 4; ++i) {                                         \
            int lin = tid + i * 256;                                          \
            int row = lin >> 3, seg = lin & 7;                                \
            uint32_t d = sa + row * 128 + (((seg ^ (row & 7))) << 4);         \
            CP_ASYNC16(d, A + (size_t)(bm + row) * LDA + k0 + seg * 8);       \
        }                                                                     \
        _Pragma("unroll")                                                     \
        for (int i = 0; i < 4; ++i) {                                         \
            int lin = tid + i * 256;                                          \
            int row = lin >> 4, chk = lin & 15;                               \
            uint32_t d = sB + row * 256 + (((chk ^ (row & 7))) << 4);         \
            CP_ASYNC16(d, B + (size_t)(k0 + row) * LDB + bn + chk * 8);       \
        }                                                                     \
    }                                                                         \
    CP_COMMIT();                                                              \
} while (0)

    T_LOAD(0); T_LOAD(1); T_LOAD(2);

    for (int ch = 0; ch < NCHUNK; ++ch) {
        CP_WAIT2();
        __syncthreads();
        T_LOAD(ch + 3);

        const uint32_t abase = sb + (uint32_t)(ch % T_NSTG) * T_STAGE;
        const uint32_t bbase = abase + T_A_TILE;
#pragma unroll
        for (int kk = 0; kk < 4; ++kk) {
            uint32_t ah[2][4];
#pragma unroll
            for (int m = 0; m < 2; ++m) {
                uint32_t r = wm + m * 16 + (lane & 15);
                uint32_t c = kk * 2 + (lane >> 4);
                ldsm_x4(ah[m], abase + r * 128 + ((c ^ (r & 7)) << 4));
            }
            uint32_t bh[4][4];
#pragma unroll
            for (int j = 0; j < 4; ++j) {
                uint32_t krow = kk * 16 + (lane & 15);
                uint32_t chk = (uint32_t)(wn >> 3) + j * 2 + (lane >> 4);
                ldsm_x4_t(bh[j], bbase + krow * 256 + ((chk ^ (krow & 7)) << 4));
            }
#pragma unroll
            for (int m = 0; m < 2; ++m)
#pragma unroll
                for (int j = 0; j < 4; ++j)
#pragma unroll
                    for (int h = 0; h < 2; ++h)
                        mma_f16(acc[m][j * 2 + h], ah[m], &bh[j][2 * h]);
        }
        __syncthreads();
    }

#pragma unroll
    for (int m = 0; m < 2; ++m) {
        const int row = bm + wm + m * 16 + (lane >> 2);
#pragma unroll
        for (int n8 = 0; n8 < 8; ++n8) {
            const int col = bn + wn + n8 * 8 + (lane & 3) * 2;
            float2 v0 = make_float2(fmaxf(acc[m][n8][0], 0.f), fmaxf(acc[m][n8][1], 0.f));
            float2 v1 = make_float2(fmaxf(acc[m][n8][2], 0.f), fmaxf(acc[m][n8][3], 0.f));
            *reinterpret_cast<float2*>(C + (size_t)row * LDC + col) = v0;
            *reinterpret_cast<float2*>(C + (size_t)(row + 8) * LDC + col) = v1;
            if (C16) {
                *reinterpret_cast<uint32_t*>(C16 + (size_t)row * LDC + col) =
                    pack_h2(__float2half(v0.x), __float2half(v0.y));
                *reinterpret_cast<uint32_t*>(C16 + (size_t)(row + 8) * LDC + col) =
                    pack_h2(__float2half(v1.x), __float2half(v1.y));
            }
        }
    }
#undef T_LOAD
}

// ===== GEMM2 (agg2): fp16 single, gathered B, fp16 epilogue into cat2 =====
#define Q_A_TILE 16384
#define Q_B_TILE 16384
#define Q_STAGE  (Q_A_TILE + Q_B_TILE)
#define Q_NSTG   6
#define Q_SMEM   (Q_NSTG * Q_STAGE)

__global__ __launch_bounds__(256, 1)
void gemm2_f16(const __half* __restrict__ A,
               const __half* __restrict__ B,
               const int* __restrict__ gidx,
               __half* __restrict__ C) {
    constexpr int NCHUNK = S2_CNT / 64;
    constexpr int LDA = S2_CNT, LDB = D_DIM, LDC = 1024;
    extern __shared__ __align__(128) char smem[];
    const uint32_t sb = smem_u32(smem);
    const int tid = threadIdx.x;
    const int wid = tid >> 5;
    const int lane = tid & 31;
    const int bm = blockIdx.y * 128;
    const int bn = blockIdx.x * 128;
    const int wm = (wid & 3) * 32;
    const int wn = (wid >> 2) * 64;

    float acc[2][8][4];
#pragma unroll
    for (int m = 0; m < 2; ++m)
#pragma unroll
        for (int n = 0; n < 8; ++n)
#pragma unroll
            for (int j = 0; j < 4; ++j) acc[m][n][j] = 0.f;

#define Q_LOAD(ch) do {                                                       \
    if ((ch) < NCHUNK) {                                                      \
        size_t k0 = (size_t)(ch) * 64;                                        \
        uint32_t sa = sb + (uint32_t)((ch) % Q_NSTG) * Q_STAGE;               \
        uint32_t sB = sa + Q_A_TILE;                                          \
        _Pragma("unroll")                                                     \
        for (int i = 0; i < 4; ++i) {                                         \
            int lin = tid + i * 256;                                          \
            int row = lin >> 3, seg = lin & 7;                                \
            uint32_t d = sa + row * 128 + (((seg ^ (row & 7))) << 4);         \
            CP_ASYNC16(d, A + (size_t)(bm + row) * LDA + k0 + seg * 8);       \
        }                                                                     \
        _Pragma("unroll")                                                     \
        for (int i = 0; i < 4; ++i) {                                         \
            int lin = tid + i * 256;                                          \
            int row = lin >> 4, chk = lin & 15;                               \
            int g = gidx[k0 + row];                                           \
            uint32_t d = sB + row * 256 + (((chk ^ (row & 7))) << 4);         \
            CP_ASYNC16(d, B + (size_t)g * LDB + bn + chk * 8);                \
        }                                                                     \
    }                                                                         \
    CP_COMMIT();                                                              \
} while (0)

    Q_LOAD(0); Q_LOAD(1); Q_LOAD(2); Q_LOAD(3); Q_LOAD(4);

    for (int ch = 0; ch < NCHUNK; ++ch) {
        CP_WAIT4();
        __syncthreads();
        Q_LOAD(ch + 5);

        const uint32_t abase = sb + (uint32_t)(ch % Q_NSTG) * Q_STAGE;
        const uint32_t bbase = abase + Q_A_TILE;
#pragma unroll
        for (int kk = 0; kk < 4; ++kk) {
            uint32_t ah[2][4];
#pragma unroll
            for (int m = 0; m < 2; ++m) {
                uint32_t r = wm + m * 16 + (lane & 15);
                uint32_t c = kk * 2 + (lane >> 4);
                ldsm_x4(ah[m], abase + r * 128 + ((c ^ (r & 7)) << 4));
            }
            uint32_t bh[4][4];
#pragma unroll
            for (int j = 0; j < 4; ++j) {
                uint32_t krow = kk * 16 + (lane & 15);
                uint32_t chk = (uint32_t)(wn >> 3) + j * 2 + (lane >> 4);
                ldsm_x4_t(bh[j], bbase + krow * 256 + ((chk ^ (krow & 7)) << 4));
            }
#pragma unroll
            for (int m = 0; m < 2; ++m)
#pragma unroll
                for (int j = 0; j < 4; ++j)
#pragma unroll
                    for (int h = 0; h < 2; ++h)
                        mma_f16(acc[m][j * 2 + h], ah[m], &bh[j][2 * h]);
        }
        __syncthreads();
    }

#pragma unroll
    for (int m = 0; m < 2; ++m) {
        const int row = bm + wm + m * 16 + (lane >> 2);
#pragma unroll
        for (int n8 = 0; n8 < 8; ++n8) {
            const int col = bn + wn + n8 * 8 + (lane & 3) * 2;
            float v0 = acc[m][n8][0] * A_INV, v1 = acc[m][n8][1] * A_INV;
            float v2 = acc[m][n8][2] * A_INV, v3 = acc[m][n8][3] * A_INV;
            *reinterpret_cast<uint32_t*>(C + (size_t)row * LDC + col) =
                pack_h2(__float2half(v0), __float2half(v1));
            *reinterpret_cast<uint32_t*>(C + (size_t)(row + 8) * LDC + col) =
                pack_h2(__float2half(v2), __float2half(v3));
        }
    }
#undef Q_LOAD
}

// ================= classifier + softmax =================
__global__ void cls_softmax_kernel(const float* __restrict__ h2,
                                   const float* __restrict__ wc,
                                   float* __restrict__ out) {
    __shared__ float sh[D_DIM];
    __shared__ float red[C_DIM];
    const int b = blockIdx.x;
    const int c = threadIdx.x;
    for (int i = c; i < D_DIM; i += C_DIM) sh[i] = h2[(size_t)b * D_DIM + i];
    __syncthreads();
    float acc = 0.f;
#pragma unroll 8
    for (int k = 0; k < D_DIM; ++k)
        acc = fmaf(sh[k], wc[(size_t)k * C_DIM + c], acc);
    red[c] = acc;
    __syncthreads();
    for (int s = C_DIM / 2; s > 0; s >>= 1) {
        if (c < s) red[c] = fmaxf(red[c], red[c + s]);
        __syncthreads();
    }
    float mx = red[0];
    __syncthreads();
    float e = expf(acc - mx);
    red[c] = e;
    __syncthreads();
    for (int s = C_DIM / 2; s > 0; s >>= 1) {
        if (c < s) red[c] += red[c + s];
        __syncthreads();
    }
    out[(size_t)b * C_DIM + c] = e / red[0];
}

// ================= launch =================
extern "C" void kernel_launch(void* const* d_in, const int* in_sizes, int n_in,
                              void* d_out, int out_size) {
    const float* features  = (const float*)d_in[0];
    const int*   src_nodes = (const int*)d_in[1];
    const int*   dst_idx1  = (const int*)d_in[2];
    const int*   src_idx1  = (const int*)d_in[3];
    const float* dif_mat1  = (const float*)d_in[4];
    const int*   dst_idx2  = (const int*)d_in[5];
    const int*   src_idx2  = (const int*)d_in[6];
    const float* dif_mat2  = (const float*)d_in[7];
    const float* w1        = (const float*)d_in[8];
    const float* w2        = (const float*)d_in[9];
    const float* w_cls     = (const float*)d_in[10];
    float* out = (float*)d_out;

    float *h1, *h2;
    uint8_t *a8, *xt8;
    __half *a2, *h1f16, *c1, *c2, *w1h, *w2h;
    cudaGetSymbolAddress((void**)&h1,    g_h1);
    cudaGetSymbolAddress((void**)&h2,    g_h2);
    cudaGetSymbolAddress((void**)&a8,    g_a8);
    cudaGetSymbolAddress((void**)&xt8,   g_xt8);
    cudaGetSymbolAddress((void**)&a2,    g_a2);
    cudaGetSymbolAddress((void**)&h1f16, g_h1f16);
    cudaGetSymbolAddress((void**)&c1,    g_c1);
    cudaGetSymbolAddress((void**)&c2,    g_c2);
    cudaGetSymbolAddress((void**)&w1h,   g_w1h);
    cudaGetSymbolAddress((void**)&w2h,   g_w2h);

    cudaFuncSetAttribute((const void*)gemm1_fp8,
                         cudaFuncAttributeMaxDynamicSharedMemorySize, P_SMEM);
    cudaFuncSetAttribute((const void*)gemm_1t_f16,
                         cudaFuncAttributeMaxDynamicSharedMemorySize, T_SMEM);
    cudaFuncSetAttribute((const void*)gemm2_f16,
                         cudaFuncAttributeMaxDynamicSharedMemorySize, Q_SMEM);

    // launches 1-3: prep (gemm1 lands 4th for the ncu snapshot)
    {
        int n8 = (B1_CNT * S1_CNT) / 8;
        scale_a8_kernel<<<n8 / 256, 256>>>(dif_mat1, a8, n8);
    }
    prep_xt8_kernel<<<dim3(S1_CNT / 128, F_DIM / 64), 128>>>(features, src_idx1, src_nodes, xt8);
    gather_c1_kernel<<<B1_CNT, 128>>>(features, dst_idx1, src_nodes, c1);

    // 4: agg1 -> c1[:, 0:512] fp16
    gemm1_fp8<<<dim3(F_DIM / 128, B1_CNT / 128), 512, P_SMEM>>>(a8, xt8, c1);

    // weights -> fp16
    f32_to_f16_kernel<<<(1024 * D_DIM / 4) / 256, 256>>>(w1, w1h, 1024 * D_DIM / 4);
    f32_to_f16_kernel<<<(1024 * D_DIM / 4) / 256, 256>>>(w2, w2h, 1024 * D_DIM / 4);

    // h1 = relu(c1 @ w1), co-emit fp16
    gemm_1t_f16<<<dim3(D_DIM / 128, B1_CNT / 128), 256, T_SMEM>>>(c1, w1h, h1, h1f16);

    // layer 2
    {
        int a8n = (B2_CNT * S2_CNT) / 8;
        scale_f16_kernel<<<(a8n + 255) / 256, 256>>>(dif_mat2, a2, a8n);
    }
    gather_c2_kernel<<<B2_CNT, 128>>>(h1f16, dst_idx2, c2);
    gemm2_f16<<<dim3(D_DIM / 128, B2_CNT / 128), 256, Q_SMEM>>>(a2, h1f16, src_idx2, c2);
    gemm_1t_f16<<<dim3(D_DIM / 128, B2_CNT / 128), 256, T_SMEM>>>(c2, w2h, h2, (__half*)nullptr);

    cls_softmax_kernel<<<B2_CNT, C_DIM>>>(h2, w_cls, out);
}